// round 14
// baseline (speedup 1.0000x reference)
#include <cuda_runtime.h>
#include <math.h>
#include <stdint.h>

#define TB 2
#define TT 2048
#define TC 1024
#define NH 16
#define HD 64
#define BHN (TB*NH)
#define MROWS (TB*TT)
#define SCALE 0.125f

#define NELEM ((size_t)BHN*TT*HD)

// Frag-major attention operands (tf32 words)
__device__ __align__(16) uint32_t g_qsh[NELEM], g_qsl[NELEM];  // q*scale hi/lo
__device__ __align__(16) uint32_t g_kfr[NELEM];    // k hi-only, K-frag uint2 layout
__device__ __align__(16) uint32_t g_kah[NELEM];    // ka hi-only, K-frag uint2 layout
__device__ __align__(16) uint32_t g_v32[NELEM];    // tf32(x) V-frag layout
__device__ __align__(16) uint32_t g_e32[NELEM];    // tf32(x[s+1]-y[s])
__device__ __align__(16) float    g_y[NELEM];
// tf32 GEMM operands (pre-converted once)
__device__ __align__(16) uint32_t g_xt[(size_t)MROWS*TC];
__device__ __align__(16) uint32_t g_wat[(size_t)TC*2*TC];
__device__ __align__(16) uint32_t g_wk2[(size_t)TC*TC];
__device__ __align__(16) uint32_t g_wpr[(size_t)TC*TC];
__device__ __align__(16) uint32_t g_ysumt[(size_t)TB*TT*TC];

__device__ __forceinline__ uint32_t f2tf32(float f) {
    uint32_t u;
    asm volatile("cvt.rna.tf32.f32 %0, %1;" : "=r"(u) : "f"(f));
    return u;
}
__device__ __forceinline__ void split_tf32(float v, uint32_t& hi, uint32_t& lo) {
    hi = f2tf32(v);
    lo = f2tf32(v - __uint_as_float(hi));
}
__device__ __forceinline__ void mma_tf32(float c[4], const uint32_t a[4],
                                         const uint32_t b[2]) {
    asm volatile(
        "mma.sync.aligned.m16n8k8.row.col.f32.tf32.tf32.f32 "
        "{%0,%1,%2,%3}, {%4,%5,%6,%7}, {%8,%9}, {%0,%1,%2,%3};"
        : "+f"(c[0]), "+f"(c[1]), "+f"(c[2]), "+f"(c[3])
        : "r"(a[0]), "r"(a[1]), "r"(a[2]), "r"(a[3]), "r"(b[0]), "r"(b[1]));
}
__device__ __forceinline__ uint32_t s2u(const void* p) {
    return (uint32_t)__cvta_generic_to_shared(p);
}
__device__ __forceinline__ void cp_async16(uint32_t dst, const void* src) {
    asm volatile("cp.async.cg.shared.global [%0], [%1], 16;"
                 :: "r"(dst), "l"(src));
}
#define CP_COMMIT() asm volatile("cp.async.commit_group;")
#define CP_WAIT0()  asm volatile("cp.async.wait_group 0;" ::: "memory")
#define CP_WAIT1()  asm volatile("cp.async.wait_group 1;" ::: "memory")

// ---- frag-layout index helpers ----
__device__ __forceinline__ size_t qfrag_idx(int tt, int dd) {
    int lane = ((tt & 7) << 2) | (dd & 3);
    int word = (((dd >> 3) + (lane & 7)) & 7) * 4
             + ((tt >> 3) & 1) + (((dd >> 2) & 1) << 1);
    return ((size_t)(tt >> 4)) * 1024 + lane * 32 + word;
}
__device__ __forceinline__ size_t kfrag_idx(int s, int d) {
    int lane = ((s & 7) << 2) | (d & 3);
    int word = (((d >> 3) + (lane >> 1)) & 7) * 2 + ((d >> 2) & 1);
    return ((size_t)(s >> 3)) * 512 + lane * 16 + word;
}
__device__ __forceinline__ size_t vfrag_idx(int s, int d) {
    int lane = ((d & 7) << 2) | (s & 3);
    int n = d >> 3;
    int grp = ((s >> 2) & 1) * 2 + (n >> 2);
    int word = ((grp + (lane >> 1)) & 3) * 4 + (n & 3);
    return ((size_t)(s >> 3)) * 512 + lane * 16 + word;
}
__device__ __forceinline__ void store_q(int bh, int tt, int dd, float qraw) {
    float qs = qraw * SCALE;
    size_t f = (size_t)bh * (TT * 64) + qfrag_idx(tt, dd);
    uint32_t h, l;
    split_tf32(qs, h, l);
    g_qsh[f] = h; g_qsl[f] = l;
}

// ---------------------------------------------------------------------------
// ONE prep kernel: tf32 conversions + V-frag scatter (block-range dispatch)
// ---------------------------------------------------------------------------
__global__ __launch_bounds__(256)
void prep_all_kernel(const float* __restrict__ x,
                     const float* __restrict__ W_attn,
                     const float* __restrict__ W_k2,
                     const float* __restrict__ W_proj)
{
    __shared__ uint32_t vs[4096];
    const int bid = blockIdx.x;
    const int tid = threadIdx.x;

    if (bid < 8192) {
        const float* src;
        uint32_t* dst;
        size_t i;
        if (bid < 4096)      { src = x;      dst = g_xt;  i = (size_t)bid * 256 + tid; }
        else if (bid < 6144) { src = W_attn; dst = g_wat; i = (size_t)(bid - 4096) * 256 + tid; }
        else if (bid < 7168) { src = W_k2;   dst = g_wk2; i = (size_t)(bid - 6144) * 256 + tid; }
        else                 { src = W_proj; dst = g_wpr; i = (size_t)(bid - 7168) * 256 + tid; }
        float4 v = ((const float4*)src)[i];
        ((uint4*)dst)[i] = make_uint4(f2tf32(v.x), f2tf32(v.y),
                                      f2tf32(v.z), f2tf32(v.w));
    } else {
        int p = bid - 8192;
        int s0 = (p & 31) * 64;
        int bh = p >> 5;
        int b = bh >> 4, h = bh & 15;
        int lr = tid >> 4, lc4 = (tid & 15) << 2;
#pragma unroll
        for (int it = 0; it < 4; it++) {
            int r = lr + it * 16;
            float4 v = *(const float4*)(x + ((size_t)b * TT + s0 + r) * TC + h * 64 + lc4);
            vs[vfrag_idx(r, lc4 + 0)] = f2tf32(v.x);
            vs[vfrag_idx(r, lc4 + 1)] = f2tf32(v.y);
            vs[vfrag_idx(r, lc4 + 2)] = f2tf32(v.z);
            vs[vfrag_idx(r, lc4 + 3)] = f2tf32(v.w);
        }
        __syncthreads();
        uint32_t* dst = g_v32 + (size_t)bh * (TT * 64) + (size_t)s0 * 64;
#pragma unroll
        for (int k = 0; k < 4; k++) {
            int o = (tid + k * 256) * 4;
            *(uint4*)(dst + o) = *(const uint4*)(vs + o);
        }
    }
}

// ---------------------------------------------------------------------------
// TF32 GEMM, 3-stage cp.async pipeline. (unchanged)
// ---------------------------------------------------------------------------
template<int MODE>
__global__ __launch_bounds__(256)
void tgemm_kernel(float* __restrict__ Cout, int M, int N, int K)
{
    extern __shared__ uint32_t smg[];
    const int tid = threadIdx.x;
    const int lane = tid & 31;
    const int warp = tid >> 5;
    const int warpM = warp >> 2, warpN = warp & 3;
    const int g = lane >> 2, t = lane & 3;
    const int bm = blockIdx.y * 128, bn = blockIdx.x * 128;

    const uint32_t* Ap = (MODE == 2) ? g_ysumt : g_xt;
    const uint32_t* Bw;
    int Nb, bnn;
    if (MODE == 0) {
        if (bn < 2 * TC) { Bw = g_wat; Nb = 2 * TC; bnn = bn; }
        else             { Bw = g_wk2; Nb = TC;     bnn = bn - 2 * TC; }
    } else {
        Bw = g_wpr; Nb = N; bnn = bn;
    }

    float acc[4][4][4];
#pragma unroll
    for (int i = 0; i < 4; i++)
#pragma unroll
        for (int j = 0; j < 4; j++)
#pragma unroll
            for (int r = 0; r < 4; r++) acc[i][j][r] = 0.f;

    auto issue = [&](int kt, int st) {
#pragma unroll
        for (int l = 0; l < 2; l++) {
            int id = tid + l * 256;
            int ar = id >> 2, ak = (id & 3) << 2;
            cp_async16(s2u(smg + st * 2560 + ar * 20 + ak),
                       Ap + (size_t)(bm + ar) * K + kt + ak);
            int br = id >> 5, bc = (id & 31) << 2;
            cp_async16(s2u(smg + 7680 + st * 2176 + br * 136 + bc),
                       Bw + (size_t)(kt + br) * Nb + bnn + bc);
        }
        CP_COMMIT();
    };

    issue(0, 0);
    issue(16, 1);
    const int nk = K >> 4;

    for (int i = 0; i < nk; i++) {
        const int st = i % 3;
        const uint32_t* Asb = smg + st * 2560;
        const uint32_t* Bsb = smg + 7680 + st * 2176;
        if (i + 1 < nk) { CP_WAIT1(); } else { CP_WAIT0(); }
        __syncthreads();
#pragma unroll
        for (int ks = 0; ks < 2; ks++) {
            const int k0 = ks * 8;
            uint32_t af[4][4], bf[4][2];
#pragma unroll
            for (int i4 = 0; i4 < 4; i4++) {
                int m0 = warpM * 64 + i4 * 16;
                af[i4][0] = Asb[(m0 + g) * 20 + k0 + t];
                af[i4][1] = Asb[(m0 + g + 8) * 20 + k0 + t];
                af[i4][2] = Asb[(m0 + g) * 20 + k0 + t + 4];
                af[i4][3] = Asb[(m0 + g + 8) * 20 + k0 + t + 4];
            }
#pragma unroll
            for (int j = 0; j < 4; j++) {
                int n0 = warpN * 32 + j * 8;
                bf[j][0] = Bsb[(k0 + t) * 136 + n0 + g];
                bf[j][1] = Bsb[(k0 + t + 4) * 136 + n0 + g];
            }
#pragma unroll
            for (int i4 = 0; i4 < 4; i4++)
#pragma unroll
                for (int j = 0; j < 4; j++)
                    mma_tf32(acc[i4][j], af[i4], bf[j]);
        }
        if (i + 2 < nk) issue((i + 2) << 4, (i + 2) % 3);
    }

    // epilogue
#pragma unroll
    for (int i = 0; i < 4; i++) {
#pragma unroll
        for (int j = 0; j < 4; j++) {
            int col = bn + warpN * 32 + j * 8 + t * 2;
#pragma unroll
            for (int half = 0; half < 2; half++) {
                int m = bm + warpM * 64 + i * 16 + g + half * 8;
                float2 v = half == 0 ? make_float2(acc[i][j][0], acc[i][j][1])
                                     : make_float2(acc[i][j][2], acc[i][j][3]);
                if (MODE == 2) {
                    *(float2*)(Cout + (size_t)m * N + col) = v;
                } else {
                    int b = m >> 11;
                    int tt = m & (TT - 1);
                    if (col < TC) {
                        int bh = b * NH + (col >> 6);
                        int dd = col & 63;
                        store_q(bh, tt, dd, v.x);
                        store_q(bh, tt, dd + 1, v.y);
                    } else if (col < 2 * TC) {
                        int nn = col - TC;
                        int bh = b * NH + (nn >> 6);
                        int dd = nn & 63;
                        size_t base = (size_t)bh * (TT * 64);
                        g_kfr[base + kfrag_idx(tt, dd)]     = f2tf32(v.x);
                        g_kfr[base + kfrag_idx(tt, dd + 1)] = f2tf32(v.y);
                    } else {
                        int nn = col - 2 * TC;
                        int bh = b * NH + (nn >> 6);
                        int dd = nn & 63;
                        float ka0 = 1.f / (1.f + __expf(-0.0025f * v.x));
                        float ka1 = 1.f / (1.f + __expf(-0.0025f * v.y));
                        size_t base = (size_t)bh * (TT * 64);
                        g_kah[base + kfrag_idx(tt, dd)]     = f2tf32(ka0);
                        g_kah[base + kfrag_idx(tt, dd + 1)] = f2tf32(ka1);
                    }
                }
            }
        }
    }
}

// ---------------------------------------------------------------------------
// Softmax flash attention. S = 2xTF32; PV = 1xTF32. Now 3 CTAs/SM
// (smem 65536 B x 3 = 196608 <= 228K; launch_bounds forces regs <= 85).
// ---------------------------------------------------------------------------
__global__ __launch_bounds__(256, 3)
void fattn_kernel(const float* __restrict__ x)
{
    extern __shared__ uint32_t smu[];
    uint32_t* Qh = smu;
    uint32_t* Ql = Qh + 4096;
    uint32_t* Kf = Ql + 4096;
    uint32_t* Vv = Kf + 4096;

    const int tid = threadIdx.x;
    const int lane = tid & 31;
    const int warp = tid >> 5;
    const int wm = warp >> 1;
    const int wn = warp & 1;
    const int g = lane >> 2;
    const int t = lane & 3;

    const int bh = blockIdx.y;
    const int b = bh >> 4, h = bh & 15;
    const int qb = (int)gridDim.x - 1 - (int)blockIdx.x;
    const int q0 = qb * 64;

    const size_t bhoff = (size_t)bh * (TT * 64);
    const uint32_t* kf_g = g_kfr + bhoff;
    const uint32_t* v_g  = g_v32 + bhoff;
    const float* vx = x + (size_t)b * TT * TC + h * HD;

    const uint32_t Qh_s = s2u(Qh), Ql_s = s2u(Ql);
    const uint32_t Kf_s = s2u(Kf), Vv_s = s2u(Vv);

    {
        const uint32_t* qhT = g_qsh + bhoff + (size_t)q0 * 64;
        const uint32_t* qlT = g_qsl + bhoff + (size_t)q0 * 64;
#pragma unroll
        for (int k = 0; k < 4; k++) {
            int o = (tid + k * 256) * 4;
            cp_async16(Qh_s + o * 4, qhT + o);
            cp_async16(Ql_s + o * 4, qlT + o);
        }
    }

    float O[8][4];
#pragma unroll
    for (int n = 0; n < 8; n++)
#pragma unroll
        for (int c = 0; c < 4; c++) O[n][c] = 0.f;
    float m_run[2] = {-1e30f, -1e30f};
    float l_run[2] = {0.f, 0.f};

    const int qrow0 = q0 + wm * 16 + g;
    const int qrow1 = qrow0 + 8;
    const int sw = wn * 32;

    for (int kt = 0; kt <= qb; kt++) {
        const int s0 = kt * 64;
        __syncthreads();

        {
            const uint32_t* kT = kf_g + (size_t)s0 * 64;
            const uint32_t* vT = v_g + (size_t)s0 * 64;
#pragma unroll
            for (int k = 0; k < 4; k++) {
                int o = (tid + k * 256) * 4;
                cp_async16(Kf_s + o * 4, kT + o);
                cp_async16(Vv_s + o * 4, vT + o);
            }
        }
        CP_COMMIT();
        CP_WAIT0();
        __syncthreads();

        // ---- S = Q @ K^T : 2xTF32 (Q exact, K hi)
        float acc[4][4];
#pragma unroll
        for (int nb = 0; nb < 4; nb++)
#pragma unroll
            for (int c = 0; c < 4; c++) acc[nb][c] = 0.f;

#pragma unroll
        for (int c = 0; c < 8; c++) {
            int qoff = wm * 1024 + lane * 32 + ((c + (lane & 7)) & 7) * 4;
            uint4 ahv = *(const uint4*)(Qh + qoff);
            uint4 alv = *(const uint4*)(Ql + qoff);
            uint32_t ah[4] = {ahv.x, ahv.y, ahv.z, ahv.w};
            uint32_t al[4] = {alv.x, alv.y, alv.z, alv.w};
#pragma unroll
            for (int nb = 0; nb < 4; nb++) {
                int koff = (wn * 4 + nb) * 512 + lane * 16
                         + ((c + (lane >> 1)) & 7) * 2;
                uint2 kk = *(const uint2*)(Kf + koff);
                uint32_t bv[2] = {kk.x, kk.y};
                mma_tf32(acc[nb], ah, bv);
                mma_tf32(acc[nb], al, bv);
            }
        }

        const bool diag = (kt == qb);
        if (diag) {
#pragma unroll
            for (int nb = 0; nb < 4; nb++) {
                int colb = s0 + sw + nb * 8 + 2 * t;
#pragma unroll
                for (int c = 0; c < 4; c++) {
                    int cc = colb + (c & 1);
                    int rr = (c >= 2) ? qrow1 : qrow0;
                    if (cc > rr) acc[nb][c] = -1e30f;
                }
            }
        }

        float mt0 = -1e30f, mt1 = -1e30f;
#pragma unroll
        for (int nb = 0; nb < 4; nb++) {
            mt0 = fmaxf(mt0, fmaxf(acc[nb][0], acc[nb][1]));
            mt1 = fmaxf(mt1, fmaxf(acc[nb][2], acc[nb][3]));
        }
#pragma unroll
        for (int off = 1; off <= 2; off <<= 1) {
            mt0 = fmaxf(mt0, __shfl_xor_sync(0xffffffffu, mt0, off));
            mt1 = fmaxf(mt1, __shfl_xor_sync(0xffffffffu, mt1, off));
        }
        float mn0 = fmaxf(m_run[0], mt0);
        float mn1 = fmaxf(m_run[1], mt1);
        float corr0 = __expf(m_run[0] - mn0);
        float corr1 = __expf(m_run[1] - mn1);
        m_run[0] = mn0; m_run[1] = mn1;

        float ls0 = 0.f, ls1 = 0.f;
#pragma unroll
        for (int nb = 0; nb < 4; nb++) {
            float p0 = __expf(acc[nb][0] - mn0);
            float p1 = __expf(acc[nb][1] - mn0);
            float p2 = __expf(acc[nb][2] - mn1);
            float p3 = __expf(acc[nb][3] - mn1);
            if (diag) {
                int colb = s0 + sw + nb * 8 + 2 * t;
                if (colb     > qrow0) p0 = 0.f;
                if (colb + 1 > qrow0) p1 = 0.f;
                if (colb     > qrow1) p2 = 0.f;
                if (colb + 1 > qrow1) p3 = 0.f;
            }
            acc[nb][0] = p0; acc[nb][1] = p1;
            acc[nb][2] = p2; acc[nb][3] = p3;
            ls0 += p0 + p1;
            ls1 += p2 + p3;
        }
#pragma unroll
        for (int off = 1; off <= 2; off <<= 1) {
            ls0 += __shfl_xor_sync(0xffffffffu, ls0, off);
            ls1 += __shfl_xor_sync(0xffffffffu, ls1, off);
        }
        l_run[0] = l_run[0] * corr0 + ls0;
        l_run[1] = l_run[1] * corr1 + ls1;
#pragma unroll
        for (int n = 0; n < 8; n++) {
            O[n][0] *= corr0; O[n][1] *= corr0;
            O[n][2] *= corr1; O[n][3] *= corr1;
        }

        // ---- O += P @ V : P hi-only (1xTF32)
#pragma unroll
        for (int nb = 0; nb < 4; nb++) {
            int src0 = (lane & ~3) | (t >> 1);
            int src2 = src0 + 2;
            float s00 = __shfl_sync(0xffffffffu, acc[nb][0], src0);
            float s01 = __shfl_sync(0xffffffffu, acc[nb][1], src0);
            float s20 = __shfl_sync(0xffffffffu, acc[nb][0], src2);
            float s21 = __shfl_sync(0xffffffffu, acc[nb][1], src2);
            float s10 = __shfl_sync(0xffffffffu, acc[nb][2], src0);
            float s11 = __shfl_sync(0xffffffffu, acc[nb][3], src0);
            float s30 = __shfl_sync(0xffffffffu, acc[nb][2], src2);
            float s31 = __shfl_sync(0xffffffffu, acc[nb][3], src2);
            bool odd = (t & 1);
            uint32_t ah[4];
            ah[0] = f2tf32(odd ? s01 : s00);
            ah[1] = f2tf32(odd ? s11 : s10);
            ah[2] = f2tf32(odd ? s21 : s20);
            ah[3] = f2tf32(odd ? s31 : s30);

            int vb = (wn * 4 + nb) * 512 + lane * 16;
            uint32_t vfr[16];
#pragma unroll
            for (int G = 0; G < 4; G++) {
                uint4 t4 = *(const uint4*)(Vv + vb + ((G + (lane >> 1)) & 3) * 4);
                vfr[G * 4 + 0] = t4.x; vfr[G * 4 + 1] = t4.y;
                vfr[G * 4 + 2] = t4.z; vfr[G * 4 + 3] = t4.w;
            }
#pragma unroll
            for (int n = 0; n < 8; n++) {
                uint32_t bv[2] = {vfr[n], vfr[8 + n]};
                mma_tf32(O[n], ah, bv);
            }
        }
    }

    __syncthreads();
    const int r0l = wm * 16 + g, r1l = r0l + 8;
    float* Ob = (float*)Qh;
    float* ml = (float*)Kf;
    if (t == 0) {
        ml[r0l * 4 + wn * 2 + 0] = m_run[0];
        ml[r0l * 4 + wn * 2 + 1] = l_run[0];
        ml[r1l * 4 + wn * 2 + 0] = m_run[1];
        ml[r1l * 4 + wn * 2 + 1] = l_run[1];
    }
    __syncthreads();
    float ma0 = ml[r0l * 4 + 0], la0 = ml[r0l * 4 + 1];
    float mb0 = ml[r0l * 4 + 2], lb0 = ml[r0l * 4 + 3];
    float ma1 = ml[r1l * 4 + 0], la1 = ml[r1l * 4 + 1];
    float mb1 = ml[r1l * 4 + 2], lb1 = ml[r1l * 4 + 3];
    float mm0 = fmaxf(ma0, mb0), mm1 = fmaxf(ma1, mb1);
    float lt0 = la0 * __expf(ma0 - mm0) + lb0 * __expf(mb0 - mm0);
    float lt1 = la1 * __expf(ma1 - mm1) + lb1 * __expf(mb1 - mm1);
    float f0 = __expf(m_run[0] - mm0);
    float f1 = __expf(m_run[1] - mm1);
#pragma unroll
    for (int n = 0; n < 8; n++) {
        O[n][0] *= f0; O[n][1] *= f0;
        O[n][2] *= f1; O[n][3] *= f1;
    }
    if (wn == 1) {
#pragma unroll
        for (int n = 0; n < 8; n++) {
            int col = n * 8 + 2 * t;
            *(float2*)(Ob + r0l * 66 + col) = make_float2(O[n][0], O[n][1]);
            *(float2*)(Ob + r1l * 66 + col) = make_float2(O[n][2], O[n][3]);
        }
    }
    __syncthreads();
    if (wn == 0) {
        float inv0 = 1.f / lt0, inv1 = 1.f / lt1;
        float* yo = g_y + (size_t)bh * TT * HD;
        uint32_t* eo = g_e32 + bhoff;
#pragma unroll
        for (int n = 0; n < 8; n++) {
            int col = n * 8 + 2 * t;
            float2 p0 = *(const float2*)(Ob + r0l * 66 + col);
            float2 p1 = *(const float2*)(Ob + r1l * 66 + col);
            float y00 = (O[n][0] + p0.x) * inv0;
            float y01 = (O[n][1] + p0.y) * inv0;
            float y10 = (O[n][2] + p1.x) * inv1;
            float y11 = (O[n][3] + p1.y) * inv1;
            *(float2*)(yo + (size_t)qrow0 * HD + col) = make_float2(y00, y01);
            *(float2*)(yo + (size_t)qrow1 * HD + col) = make_float2(y10, y11);
            float e00 = 0.f, e01 = 0.f, e10 = 0.f, e11 = 0.f;
            if (qrow0 + 1 < TT) {
                float2 xv = *(const float2*)(vx + (size_t)(qrow0 + 1) * TC + col);
                e00 = xv.x - y00; e01 = xv.y - y01;
            }
            if (qrow1 + 1 < TT) {
                float2 xv = *(const float2*)(vx + (size_t)(qrow1 + 1) * TC + col);
                e10 = xv.x - y10; e11 = xv.y - y11;
            }
            eo[vfrag_idx(qrow0, col)]     = f2tf32(e00);
            eo[vfrag_idx(qrow0, col + 1)] = f2tf32(e01);
            eo[vfrag_idx(qrow1, col)]     = f2tf32(e10);
            eo[vfrag_idx(qrow1, col + 1)] = f2tf32(e11);
        }
    }
}

// ---------------------------------------------------------------------------
// ARMA attention: 1xTF32 S, 1xTF32 PV, 3 CTAs/SM, TWO-STAGE pipeline over
// 32-row s-tiles (Ka/Vv [2][2048]); loads of tile st+2 overlap compute of st.
// smem: Qa(4096) + Ka(2x2048) + Vv(2x2048) = 49152 B (unchanged).
// ---------------------------------------------------------------------------
__global__ __launch_bounds__(256, 3)
void arma_kernel()
{
    extern __shared__ uint32_t smu[];
    uint32_t* Qa = smu;            // 4096
    uint32_t* Ka = Qa + 4096;      // [2][2048]
    uint32_t* Vv = Ka + 4096;      // [2][2048]

    const int tid = threadIdx.x;
    const int lane = tid & 31;
    const int warp = tid >> 5;
    const int wm = warp >> 1;
    const int wn = warp & 1;
    const int g = lane >> 2;
    const int t = lane & 3;

    const int bh = blockIdx.y;
    const int b = bh >> 4, h = bh & 15;
    const int qb = (int)gridDim.x - 1 - (int)blockIdx.x;
    const int q0 = qb * 64;
    const int nst = 2 * (qb + 1);      // 32-row s-tiles

    const size_t bhoff = (size_t)bh * (TT * 64);
    const uint32_t* ka_g = g_kah + bhoff;
    const uint32_t* e_g  = g_e32 + bhoff;
    const float* yb = g_y + (size_t)bh * TT * HD;

    const uint32_t Ka_s = s2u(Ka), Vv_s = s2u(Vv);

    // ---- stage Qa: reconstruct qs = hi+lo, apply leaky-min, round once
    {
        const uint32_t* qhT = g_qsh + bhoff + (size_t)q0 * 64;
        const uint32_t* qlT = g_qsl + bhoff + (size_t)q0 * 64;
#pragma unroll
        for (int k = 0; k < 4; k++) {
            int o = (tid + k * 256) * 4;
            uint4 hv = *(const uint4*)(qhT + o);
            uint4 lv = *(const uint4*)(qlT + o);
            float q0f = __uint_as_float(hv.x) + __uint_as_float(lv.x);
            float q1f = __uint_as_float(hv.y) + __uint_as_float(lv.y);
            float q2f = __uint_as_float(hv.z) + __uint_as_float(lv.z);
            float q3f = __uint_as_float(hv.w) + __uint_as_float(lv.w);
            *(uint4*)(Qa + o) = make_uint4(
                f2tf32(fminf(q0f, 0.02f * q0f)),
                f2tf32(fminf(q1f, 0.02f * q1f)),
                f2tf32(fminf(q2f, 0.02f * q2f)),
                f2tf32(fminf(q3f, 0.02f * q3f)));
        }
    }

    // ---- prologue: stage tiles 0 and 1 (nst >= 2 always)
#pragma unroll
    for (int st = 0; st < 2; st++) {
#pragma unroll
        for (int k = 0; k < 2; k++) {
            int o = (tid + k * 256) * 4;
            cp_async16(Ka_s + (st * 2048 + o) * 4, ka_g + (size_t)st * 2048 + o);
            cp_async16(Vv_s + (st * 2048 + o) * 4, e_g + (size_t)st * 2048 + o);
        }
        CP_COMMIT();
    }

    float O[8][4];
#pragma unroll
    for (int n = 0; n < 8; n++)
#pragma unroll
        for (int c = 0; c < 4; c++) O[n][c] = 0.f;

    const int qrow0 = q0 + wm * 16 + g;
    const int qrow1 = qrow0 + 8;

    for (int st = 0; st < nst; st++) {
        const int stage = st & 1;
        const int s0 = st * 32;
        if (st + 2 < nst) { CP_WAIT1(); } else { CP_WAIT0(); }
        __syncthreads();

        // ---- S = Qa @ Ka^T over this warp's 16 s-cols (1xTF32)
        float acc[2][4];
#pragma unroll
        for (int nb = 0; nb < 2; nb++)
#pragma unroll
            for (int c = 0; c < 4; c++) acc[nb][c] = 0.f;

#pragma unroll
        for (int c = 0; c < 8; c++) {
            int qoff = wm * 1024 + lane * 32 + ((c + (lane & 7)) & 7) * 4;
            uint4 ahv = *(const uint4*)(Qa + qoff);
            uint32_t ah[4] = {ahv.x, ahv.y, ahv.z, ahv.w};
#pragma unroll
            for (int nb = 0; nb < 2; nb++) {
                int koff = stage * 2048 + (wn * 2 + nb) * 512 + lane * 16
                         + ((c + (lane >> 1)) & 7) * 2;
                uint2 kk = *(const uint2*)(Ka + koff);
                uint32_t bv[2] = {kk.x, kk.y};
                mma_tf32(acc[nb], ah, bv);
            }
        }

        const bool diag = (st >= 2 * qb);   // last two tiles cover rows [q0,q0+64)
        if (diag) {
#pragma unroll
            for (int nb = 0; nb < 2; nb++) {
                int colb = s0 + wn * 16 + nb * 8 + 2 * t;
#pragma unroll
                for (int c = 0; c < 4; c++) {
                    int cc = colb + (c & 1);
                    int rr = (c >= 2) ? qrow1 : qrow0;
                    if (cc >= rr) acc[nb][c] = 0.f;
                }
            }
        }

        // ---- O += P @ E : P hi-only (1xTF32)
#pragma unroll
        for (int nb = 0; nb < 2; nb++) {
            int src0 = (lane & ~3) | (t >> 1);
            int src2 = src0 + 2;
            float s00 = __shfl_sync(0xffffffffu, acc[nb][0], src0);
            float s01 = __shfl_sync(0xffffffffu, acc[nb][1], src0);
            float s20 = __shfl_sync(0xffffffffu, acc[nb][0], src2);
            float s21 = __shfl_sync(0xffffffffu, acc[nb][1], src2);
            float s10 = __shfl_sync(0xffffffffu, acc[nb][2], src0);
            float s11 = __shfl_sync(0xffffffffu, acc[nb][3], src0);
            float s30 = __shfl_sync(0xffffffffu, acc[nb][2], src2);
            float s31 = __shfl_sync(0xffffffffu, acc[nb][3], src2);
            bool odd = (t & 1);
            uint32_t ah[4];
            ah[0] = f2tf32(odd ? s01 : s00);
            ah[1] = f2tf32(odd ? s11 : s10);
            ah[2] = f2tf32(odd ? s21 : s20);
            ah[3] = f2tf32(odd ? s31 : s30);

            int vb = stage * 2048 + (wn * 2 + nb) * 512 + lane * 16;
            uint32_t vfr[16];
#pragma unroll
            for (int G = 0; G < 4; G++) {
                uint4 t4 = *(const uint4*)(Vv + vb + ((G + (lane >> 1)) & 3) * 4);
                vfr[G * 4 + 0] = t4.x; vfr[G * 4 + 1] = t4.y;
                vfr[G * 4 + 2] = t4.z; vfr[G * 4 + 3] = t4.w;
            }
#pragma unroll
            for (int n = 0; n < 8; n++) {
                uint32_t bv[2] = {vfr[n], vfr[8 + n]};
                mma_tf32(O[n], ah, bv);
            }
        }

        __syncthreads();   // all warps done reading buffer `stage`
        if (st + 2 < nst) {
#pragma unroll
            for (int k = 0; k < 2; k++) {
                int o = (tid + k * 256) * 4;
                cp_async16(Ka_s + (stage * 2048 + o) * 4,
                           ka_g + (size_t)(st + 2) * 2048 + o);
                cp_async16(Vv_s + (stage * 2048 + o) * 4,
                           e_g + (size_t)(st + 2) * 2048 + o);
            }
        }
        CP_COMMIT();
    }

    // ---- merge wn stripes, write ysumt = tf32(y + y2)
    __syncthreads();
    const int r0l = wm * 16 + g, r1l = r0l + 8;
    float* Ob = (float*)smu;   // pitch 66, 4224 words < 12288
    if (wn == 1) {
#pragma unroll
        for (int n = 0; n < 8; n++) {
            int col = n * 8 + 2 * t;
            *(float2*)(Ob + r0l * 66 + col) = make_float2(O[n][0], O[n][1]);
            *(float2*)(Ob + r1l * 66 + col) = make_float2(O[n][2], O[n][3]);
        }
    }
    __syncthreads();
    if (wn == 0) {
        uint32_t* yo = g_ysumt + (size_t)b * TT * TC + h * HD;
#pragma unroll
        for (int n = 0; n < 8; n++) {
            int col = n * 8 + 2 * t;
            float2 p0 = *(const float2*)(Ob + r0l * 66 + col);
            float2 p1 = *(const float2*)(Ob + r1l * 66 + col);
            float2 y0 = *(const float2*)(yb + (size_t)qrow0 * HD + col);
            float2 y1 = *(const float2*)(yb + (size_t)qrow1 * HD + col);
            *(uint2*)(yo + (size_t)qrow0 * TC + col) =
                make_uint2(f2tf32(O[n][0] + p0.x + y0.x),
                           f2tf32(O[n][1] + p0.y + y0.y));
            *(uint2*)(yo + (size_t)qrow1 * TC + col) =
                make_uint2(f2tf32(O[n][2] + p1.x + y1.x),
                           f2tf32(O[n][3] + p1.y + y1.y));
        }
    }
}

// ---------------------------------------------------------------------------
extern "C" void kernel_launch(void* const* d_in, const int* in_sizes, int n_in,
                              void* d_out, int out_size)
{
    (void)in_sizes; (void)n_in; (void)out_size;
    const float* x      = (const float*)d_in[0];
    const float* W_attn = (const float*)d_in[1];
    const float* W_k2   = (const float*)d_in[2];
    const float* W_proj = (const float*)d_in[3];
    float* out = (float*)d_out;

    const int smem_attn = 16384 * (int)sizeof(uint32_t);  // 65536 B
    const int smem_arma = 12288 * (int)sizeof(uint32_t);  // 49152 B
    const int smem_gemm = (3 * 2560 + 3 * 2176) * (int)sizeof(uint32_t);
    cudaFuncSetAttribute(fattn_kernel,
                         cudaFuncAttributeMaxDynamicSharedMemorySize, smem_attn);
    cudaFuncSetAttribute(arma_kernel,
                         cudaFuncAttributeMaxDynamicSharedMemorySize, smem_arma);
    cudaFuncSetAttribute(tgemm_kernel<0>,
                         cudaFuncAttributeMaxDynamicSharedMemorySize, smem_gemm);
    cudaFuncSetAttribute(tgemm_kernel<2>,
                         cudaFuncAttributeMaxDynamicSharedMemorySize, smem_gemm);

    prep_all_kernel<<<9216, 256>>>(x, W_attn, W_k2, W_proj);
    tgemm_kernel<0><<<dim3(3 * TC / 128, MROWS / 128), 256, smem_gemm>>>(
        nullptr, MROWS, 3 * TC, TC);
    fattn_kernel<<<dim3(TT / 64, BHN), 256, smem_attn>>>(x);
    arma_kernel<<<dim3(TT / 64, BHN), 256, smem_arma>>>();
    tgemm_kernel<2><<<dim3(TC / 128, MROWS / 128), 256, smem_gemm>>>(
        out, MROWS, TC, TC);
}

// round 15
// speedup vs baseline: 1.0744x; 1.0744x over previous
#include <cuda_runtime.h>
#include <math.h>
#include <stdint.h>

#define TB 2
#define TT 2048
#define TC 1024
#define NH 16
#define HD 64
#define BHN (TB*NH)
#define MROWS (TB*TT)
#define SCALE 0.125f

#define NELEM ((size_t)BHN*TT*HD)

// Frag-major attention operands (tf32 words)
__device__ __align__(16) uint32_t g_qsh[NELEM], g_qsl[NELEM];  // q*scale hi/lo
__device__ __align__(16) uint32_t g_kfr[NELEM];    // k hi-only, K-frag uint2 layout
__device__ __align__(16) uint32_t g_kah[NELEM];    // ka hi-only, K-frag uint2 layout
__device__ __align__(16) uint32_t g_v32[NELEM];    // tf32(x) V-frag layout
__device__ __align__(16) uint32_t g_e32[NELEM];    // tf32(x[s+1]-y[s])
__device__ __align__(16) float    g_y[NELEM];
// tf32 GEMM operands (pre-converted once)
__device__ __align__(16) uint32_t g_xt[(size_t)MROWS*TC];
__device__ __align__(16) uint32_t g_wat[(size_t)TC*2*TC];
__device__ __align__(16) uint32_t g_wk2[(size_t)TC*TC];
__device__ __align__(16) uint32_t g_wpr[(size_t)TC*TC];
__device__ __align__(16) uint32_t g_ysumt[(size_t)TB*TT*TC];

__device__ __forceinline__ uint32_t f2tf32(float f) {
    uint32_t u;
    asm volatile("cvt.rna.tf32.f32 %0, %1;" : "=r"(u) : "f"(f));
    return u;
}
__device__ __forceinline__ void split_tf32(float v, uint32_t& hi, uint32_t& lo) {
    hi = f2tf32(v);
    lo = f2tf32(v - __uint_as_float(hi));
}
__device__ __forceinline__ void mma_tf32(float c[4], const uint32_t a[4],
                                         const uint32_t b[2]) {
    asm volatile(
        "mma.sync.aligned.m16n8k8.row.col.f32.tf32.tf32.f32 "
        "{%0,%1,%2,%3}, {%4,%5,%6,%7}, {%8,%9}, {%0,%1,%2,%3};"
        : "+f"(c[0]), "+f"(c[1]), "+f"(c[2]), "+f"(c[3])
        : "r"(a[0]), "r"(a[1]), "r"(a[2]), "r"(a[3]), "r"(b[0]), "r"(b[1]));
}
__device__ __forceinline__ uint32_t s2u(const void* p) {
    return (uint32_t)__cvta_generic_to_shared(p);
}
__device__ __forceinline__ void cp_async16(uint32_t dst, const void* src) {
    asm volatile("cp.async.cg.shared.global [%0], [%1], 16;"
                 :: "r"(dst), "l"(src));
}
#define CP_COMMIT() asm volatile("cp.async.commit_group;")
#define CP_WAIT0()  asm volatile("cp.async.wait_group 0;" ::: "memory")
#define CP_WAIT1()  asm volatile("cp.async.wait_group 1;" ::: "memory")

// ---- frag-layout index helpers ----
__device__ __forceinline__ size_t qfrag_idx(int tt, int dd) {
    int lane = ((tt & 7) << 2) | (dd & 3);
    int word = (((dd >> 3) + (lane & 7)) & 7) * 4
             + ((tt >> 3) & 1) + (((dd >> 2) & 1) << 1);
    return ((size_t)(tt >> 4)) * 1024 + lane * 32 + word;
}
__device__ __forceinline__ size_t kfrag_idx(int s, int d) {
    int lane = ((s & 7) << 2) | (d & 3);
    int word = (((d >> 3) + (lane >> 1)) & 7) * 2 + ((d >> 2) & 1);
    return ((size_t)(s >> 3)) * 512 + lane * 16 + word;
}
__device__ __forceinline__ size_t vfrag_idx(int s, int d) {
    int lane = ((d & 7) << 2) | (s & 3);
    int n = d >> 3;
    int grp = ((s >> 2) & 1) * 2 + (n >> 2);
    int word = ((grp + (lane >> 1)) & 3) * 4 + (n & 3);
    return ((size_t)(s >> 3)) * 512 + lane * 16 + word;
}
__device__ __forceinline__ void store_q(int bh, int tt, int dd, float qraw) {
    float qs = qraw * SCALE;
    size_t f = (size_t)bh * (TT * 64) + qfrag_idx(tt, dd);
    uint32_t h, l;
    split_tf32(qs, h, l);
    g_qsh[f] = h; g_qsl[f] = l;
}

// ---------------------------------------------------------------------------
// ONE prep kernel: tf32 conversions + V-frag scatter (block-range dispatch)
// ---------------------------------------------------------------------------
__global__ __launch_bounds__(256)
void prep_all_kernel(const float* __restrict__ x,
                     const float* __restrict__ W_attn,
                     const float* __restrict__ W_k2,
                     const float* __restrict__ W_proj)
{
    __shared__ uint32_t vs[4096];
    const int bid = blockIdx.x;
    const int tid = threadIdx.x;

    if (bid < 8192) {
        const float* src;
        uint32_t* dst;
        size_t i;
        if (bid < 4096)      { src = x;      dst = g_xt;  i = (size_t)bid * 256 + tid; }
        else if (bid < 6144) { src = W_attn; dst = g_wat; i = (size_t)(bid - 4096) * 256 + tid; }
        else if (bid < 7168) { src = W_k2;   dst = g_wk2; i = (size_t)(bid - 6144) * 256 + tid; }
        else                 { src = W_proj; dst = g_wpr; i = (size_t)(bid - 7168) * 256 + tid; }
        float4 v = ((const float4*)src)[i];
        ((uint4*)dst)[i] = make_uint4(f2tf32(v.x), f2tf32(v.y),
                                      f2tf32(v.z), f2tf32(v.w));
    } else {
        int p = bid - 8192;
        int s0 = (p & 31) * 64;
        int bh = p >> 5;
        int b = bh >> 4, h = bh & 15;
        int lr = tid >> 4, lc4 = (tid & 15) << 2;
#pragma unroll
        for (int it = 0; it < 4; it++) {
            int r = lr + it * 16;
            float4 v = *(const float4*)(x + ((size_t)b * TT + s0 + r) * TC + h * 64 + lc4);
            vs[vfrag_idx(r, lc4 + 0)] = f2tf32(v.x);
            vs[vfrag_idx(r, lc4 + 1)] = f2tf32(v.y);
            vs[vfrag_idx(r, lc4 + 2)] = f2tf32(v.z);
            vs[vfrag_idx(r, lc4 + 3)] = f2tf32(v.w);
        }
        __syncthreads();
        uint32_t* dst = g_v32 + (size_t)bh * (TT * 64) + (size_t)s0 * 64;
#pragma unroll
        for (int k = 0; k < 4; k++) {
            int o = (tid + k * 256) * 4;
            *(uint4*)(dst + o) = *(const uint4*)(vs + o);
        }
    }
}

// ---------------------------------------------------------------------------
// TF32 GEMM, 3-stage cp.async pipeline. (unchanged)
// ---------------------------------------------------------------------------
template<int MODE>
__global__ __launch_bounds__(256)
void tgemm_kernel(float* __restrict__ Cout, int M, int N, int K)
{
    extern __shared__ uint32_t smg[];
    const int tid = threadIdx.x;
    const int lane = tid & 31;
    const int warp = tid >> 5;
    const int warpM = warp >> 2, warpN = warp & 3;
    const int g = lane >> 2, t = lane & 3;
    const int bm = blockIdx.y * 128, bn = blockIdx.x * 128;

    const uint32_t* Ap = (MODE == 2) ? g_ysumt : g_xt;
    const uint32_t* Bw;
    int Nb, bnn;
    if (MODE == 0) {
        if (bn < 2 * TC) { Bw = g_wat; Nb = 2 * TC; bnn = bn; }
        else             { Bw = g_wk2; Nb = TC;     bnn = bn - 2 * TC; }
    } else {
        Bw = g_wpr; Nb = N; bnn = bn;
    }

    float acc[4][4][4];
#pragma unroll
    for (int i = 0; i < 4; i++)
#pragma unroll
        for (int j = 0; j < 4; j++)
#pragma unroll
            for (int r = 0; r < 4; r++) acc[i][j][r] = 0.f;

    auto issue = [&](int kt, int st) {
#pragma unroll
        for (int l = 0; l < 2; l++) {
            int id = tid + l * 256;
            int ar = id >> 2, ak = (id & 3) << 2;
            cp_async16(s2u(smg + st * 2560 + ar * 20 + ak),
                       Ap + (size_t)(bm + ar) * K + kt + ak);
            int br = id >> 5, bc = (id & 31) << 2;
            cp_async16(s2u(smg + 7680 + st * 2176 + br * 136 + bc),
                       Bw + (size_t)(kt + br) * Nb + bnn + bc);
        }
        CP_COMMIT();
    };

    issue(0, 0);
    issue(16, 1);
    const int nk = K >> 4;

    for (int i = 0; i < nk; i++) {
        const int st = i % 3;
        const uint32_t* Asb = smg + st * 2560;
        const uint32_t* Bsb = smg + 7680 + st * 2176;
        if (i + 1 < nk) { CP_WAIT1(); } else { CP_WAIT0(); }
        __syncthreads();
#pragma unroll
        for (int ks = 0; ks < 2; ks++) {
            const int k0 = ks * 8;
            uint32_t af[4][4], bf[4][2];
#pragma unroll
            for (int i4 = 0; i4 < 4; i4++) {
                int m0 = warpM * 64 + i4 * 16;
                af[i4][0] = Asb[(m0 + g) * 20 + k0 + t];
                af[i4][1] = Asb[(m0 + g + 8) * 20 + k0 + t];
                af[i4][2] = Asb[(m0 + g) * 20 + k0 + t + 4];
                af[i4][3] = Asb[(m0 + g + 8) * 20 + k0 + t + 4];
            }
#pragma unroll
            for (int j = 0; j < 4; j++) {
                int n0 = warpN * 32 + j * 8;
                bf[j][0] = Bsb[(k0 + t) * 136 + n0 + g];
                bf[j][1] = Bsb[(k0 + t + 4) * 136 + n0 + g];
            }
#pragma unroll
            for (int i4 = 0; i4 < 4; i4++)
#pragma unroll
                for (int j = 0; j < 4; j++)
                    mma_tf32(acc[i4][j], af[i4], bf[j]);
        }
        if (i + 2 < nk) issue((i + 2) << 4, (i + 2) % 3);
    }

    // epilogue
#pragma unroll
    for (int i = 0; i < 4; i++) {
#pragma unroll
        for (int j = 0; j < 4; j++) {
            int col = bn + warpN * 32 + j * 8 + t * 2;
#pragma unroll
            for (int half = 0; half < 2; half++) {
                int m = bm + warpM * 64 + i * 16 + g + half * 8;
                float2 v = half == 0 ? make_float2(acc[i][j][0], acc[i][j][1])
                                     : make_float2(acc[i][j][2], acc[i][j][3]);
                if (MODE == 2) {
                    *(float2*)(Cout + (size_t)m * N + col) = v;
                } else {
                    int b = m >> 11;
                    int tt = m & (TT - 1);
                    if (col < TC) {
                        int bh = b * NH + (col >> 6);
                        int dd = col & 63;
                        store_q(bh, tt, dd, v.x);
                        store_q(bh, tt, dd + 1, v.y);
                    } else if (col < 2 * TC) {
                        int nn = col - TC;
                        int bh = b * NH + (nn >> 6);
                        int dd = nn & 63;
                        size_t base = (size_t)bh * (TT * 64);
                        g_kfr[base + kfrag_idx(tt, dd)]     = f2tf32(v.x);
                        g_kfr[base + kfrag_idx(tt, dd + 1)] = f2tf32(v.y);
                    } else {
                        int nn = col - 2 * TC;
                        int bh = b * NH + (nn >> 6);
                        int dd = nn & 63;
                        float ka0 = 1.f / (1.f + __expf(-0.0025f * v.x));
                        float ka1 = 1.f / (1.f + __expf(-0.0025f * v.y));
                        size_t base = (size_t)bh * (TT * 64);
                        g_kah[base + kfrag_idx(tt, dd)]     = f2tf32(ka0);
                        g_kah[base + kfrag_idx(tt, dd + 1)] = f2tf32(ka1);
                    }
                }
            }
        }
    }
}

// ---------------------------------------------------------------------------
// Softmax flash attention. S = 1xTF32 (Q hi, K hi); PV = 1xTF32 (P hi, V hi).
// smem: Qh(4096) + Kf(4096) + Vv(4096) = 49152 B -> 3 CTAs/SM.
// ---------------------------------------------------------------------------
__global__ __launch_bounds__(256, 3)
void fattn_kernel(const float* __restrict__ x)
{
    extern __shared__ uint32_t smu[];
    uint32_t* Qh = smu;
    uint32_t* Kf = Qh + 4096;
    uint32_t* Vv = Kf + 4096;

    const int tid = threadIdx.x;
    const int lane = tid & 31;
    const int warp = tid >> 5;
    const int wm = warp >> 1;
    const int wn = warp & 1;
    const int g = lane >> 2;
    const int t = lane & 3;

    const int bh = blockIdx.y;
    const int b = bh >> 4, h = bh & 15;
    const int qb = (int)gridDim.x - 1 - (int)blockIdx.x;
    const int q0 = qb * 64;

    const size_t bhoff = (size_t)bh * (TT * 64);
    const uint32_t* kf_g = g_kfr + bhoff;
    const uint32_t* v_g  = g_v32 + bhoff;
    const float* vx = x + (size_t)b * TT * TC + h * HD;

    const uint32_t Qh_s = s2u(Qh);
    const uint32_t Kf_s = s2u(Kf), Vv_s = s2u(Vv);

    {
        const uint32_t* qhT = g_qsh + bhoff + (size_t)q0 * 64;
#pragma unroll
        for (int k = 0; k < 4; k++) {
            int o = (tid + k * 256) * 4;
            cp_async16(Qh_s + o * 4, qhT + o);
        }
    }

    float O[8][4];
#pragma unroll
    for (int n = 0; n < 8; n++)
#pragma unroll
        for (int c = 0; c < 4; c++) O[n][c] = 0.f;
    float m_run[2] = {-1e30f, -1e30f};
    float l_run[2] = {0.f, 0.f};

    const int qrow0 = q0 + wm * 16 + g;
    const int qrow1 = qrow0 + 8;
    const int sw = wn * 32;

    for (int kt = 0; kt <= qb; kt++) {
        const int s0 = kt * 64;
        __syncthreads();

        {
            const uint32_t* kT = kf_g + (size_t)s0 * 64;
            const uint32_t* vT = v_g + (size_t)s0 * 64;
#pragma unroll
            for (int k = 0; k < 4; k++) {
                int o = (tid + k * 256) * 4;
                cp_async16(Kf_s + o * 4, kT + o);
                cp_async16(Vv_s + o * 4, vT + o);
            }
        }
        CP_COMMIT();
        CP_WAIT0();
        __syncthreads();

        // ---- S = Q @ K^T : 1xTF32 (Q hi, K hi)
        float acc[4][4];
#pragma unroll
        for (int nb = 0; nb < 4; nb++)
#pragma unroll
            for (int c = 0; c < 4; c++) acc[nb][c] = 0.f;

#pragma unroll
        for (int c = 0; c < 8; c++) {
            int qoff = wm * 1024 + lane * 32 + ((c + (lane & 7)) & 7) * 4;
            uint4 ahv = *(const uint4*)(Qh + qoff);
            uint32_t ah[4] = {ahv.x, ahv.y, ahv.z, ahv.w};
#pragma unroll
            for (int nb = 0; nb < 4; nb++) {
                int koff = (wn * 4 + nb) * 512 + lane * 16
                         + ((c + (lane >> 1)) & 7) * 2;
                uint2 kk = *(const uint2*)(Kf + koff);
                uint32_t bv[2] = {kk.x, kk.y};
                mma_tf32(acc[nb], ah, bv);
            }
        }

        const bool diag = (kt == qb);
        if (diag) {
#pragma unroll
            for (int nb = 0; nb < 4; nb++) {
                int colb = s0 + sw + nb * 8 + 2 * t;
#pragma unroll
                for (int c = 0; c < 4; c++) {
                    int cc = colb + (c & 1);
                    int rr = (c >= 2) ? qrow1 : qrow0;
                    if (cc > rr) acc[nb][c] = -1e30f;
                }
            }
        }

        float mt0 = -1e30f, mt1 = -1e30f;
#pragma unroll
        for (int nb = 0; nb < 4; nb++) {
            mt0 = fmaxf(mt0, fmaxf(acc[nb][0], acc[nb][1]));
            mt1 = fmaxf(mt1, fmaxf(acc[nb][2], acc[nb][3]));
        }
#pragma unroll
        for (int off = 1; off <= 2; off <<= 1) {
            mt0 = fmaxf(mt0, __shfl_xor_sync(0xffffffffu, mt0, off));
            mt1 = fmaxf(mt1, __shfl_xor_sync(0xffffffffu, mt1, off));
        }
        float mn0 = fmaxf(m_run[0], mt0);
        float mn1 = fmaxf(m_run[1], mt1);
        float corr0 = __expf(m_run[0] - mn0);
        float corr1 = __expf(m_run[1] - mn1);
        m_run[0] = mn0; m_run[1] = mn1;

        float ls0 = 0.f, ls1 = 0.f;
#pragma unroll
        for (int nb = 0; nb < 4; nb++) {
            float p0 = __expf(acc[nb][0] - mn0);
            float p1 = __expf(acc[nb][1] - mn0);
            float p2 = __expf(acc[nb][2] - mn1);
            float p3 = __expf(acc[nb][3] - mn1);
            if (diag) {
                int colb = s0 + sw + nb * 8 + 2 * t;
                if (colb     > qrow0) p0 = 0.f;
                if (colb + 1 > qrow0) p1 = 0.f;
                if (colb     > qrow1) p2 = 0.f;
                if (colb + 1 > qrow1) p3 = 0.f;
            }
            acc[nb][0] = p0; acc[nb][1] = p1;
            acc[nb][2] = p2; acc[nb][3] = p3;
            ls0 += p0 + p1;
            ls1 += p2 + p3;
        }
#pragma unroll
        for (int off = 1; off <= 2; off <<= 1) {
            ls0 += __shfl_xor_sync(0xffffffffu, ls0, off);
            ls1 += __shfl_xor_sync(0xffffffffu, ls1, off);
        }
        l_run[0] = l_run[0] * corr0 + ls0;
        l_run[1] = l_run[1] * corr1 + ls1;
#pragma unroll
        for (int n = 0; n < 8; n++) {
            O[n][0] *= corr0; O[n][1] *= corr0;
            O[n][2] *= corr1; O[n][3] *= corr1;
        }

        // ---- O += P @ V : P hi-only (1xTF32)
#pragma unroll
        for (int nb = 0; nb < 4; nb++) {
            int src0 = (lane & ~3) | (t >> 1);
            int src2 = src0 + 2;
            float s00 = __shfl_sync(0xffffffffu, acc[nb][0], src0);
            float s01 = __shfl_sync(0xffffffffu, acc[nb][1], src0);
            float s20 = __shfl_sync(0xffffffffu, acc[nb][0], src2);
            float s21 = __shfl_sync(0xffffffffu, acc[nb][1], src2);
            float s10 = __shfl_sync(0xffffffffu, acc[nb][2], src0);
            float s11 = __shfl_sync(0xffffffffu, acc[nb][3], src0);
            float s30 = __shfl_sync(0xffffffffu, acc[nb][2], src2);
            float s31 = __shfl_sync(0xffffffffu, acc[nb][3], src2);
            bool odd = (t & 1);
            uint32_t ah[4];
            ah[0] = f2tf32(odd ? s01 : s00);
            ah[1] = f2tf32(odd ? s11 : s10);
            ah[2] = f2tf32(odd ? s21 : s20);
            ah[3] = f2tf32(odd ? s31 : s30);

            int vb = (wn * 4 + nb) * 512 + lane * 16;
            uint32_t vfr[16];
#pragma unroll
            for (int G = 0; G < 4; G++) {
                uint4 t4 = *(const uint4*)(Vv + vb + ((G + (lane >> 1)) & 3) * 4);
                vfr[G * 4 + 0] = t4.x; vfr[G * 4 + 1] = t4.y;
                vfr[G * 4 + 2] = t4.z; vfr[G * 4 + 3] = t4.w;
            }
#pragma unroll
            for (int n = 0; n < 8; n++) {
                uint32_t bv[2] = {vfr[n], vfr[8 + n]};
                mma_tf32(O[n], ah, bv);
            }
        }
    }

    __syncthreads();
    const int r0l = wm * 16 + g, r1l = r0l + 8;
    float* Ob = (float*)smu;       // pitch 66, 4224 words < 8192 (Qh+Kf)
    float* ml = (float*)Vv;        // m/l exchange in Vv region
    if (t == 0) {
        ml[r0l * 4 + wn * 2 + 0] = m_run[0];
        ml[r0l * 4 + wn * 2 + 1] = l_run[0];
        ml[r1l * 4 + wn * 2 + 0] = m_run[1];
        ml[r1l * 4 + wn * 2 + 1] = l_run[1];
    }
    __syncthreads();
    float ma0 = ml[r0l * 4 + 0], la0 = ml[r0l * 4 + 1];
    float mb0 = ml[r0l * 4 + 2], lb0 = ml[r0l * 4 + 3];
    float ma1 = ml[r1l * 4 + 0], la1 = ml[r1l * 4 + 1];
    float mb1 = ml[r1l * 4 + 2], lb1 = ml[r1l * 4 + 3];
    float mm0 = fmaxf(ma0, mb0), mm1 = fmaxf(ma1, mb1);
    float lt0 = la0 * __expf(ma0 - mm0) + lb0 * __expf(mb0 - mm0);
    float lt1 = la1 * __expf(ma1 - mm1) + lb1 * __expf(mb1 - mm1);
    float f0 = __expf(m_run[0] - mm0);
    float f1 = __expf(m_run[1] - mm1);
#pragma unroll
    for (int n = 0; n < 8; n++) {
        O[n][0] *= f0; O[n][1] *= f0;
        O[n][2] *= f1; O[n][3] *= f1;
    }
    if (wn == 1) {
#pragma unroll
        for (int n = 0; n < 8; n++) {
            int col = n * 8 + 2 * t;
            *(float2*)(Ob + r0l * 66 + col) = make_float2(O[n][0], O[n][1]);
            *(float2*)(Ob + r1l * 66 + col) = make_float2(O[n][2], O[n][3]);
        }
    }
    __syncthreads();
    if (wn == 0) {
        float inv0 = 1.f / lt0, inv1 = 1.f / lt1;
        float* yo = g_y + (size_t)bh * TT * HD;
        uint32_t* eo = g_e32 + bhoff;
#pragma unroll
        for (int n = 0; n < 8; n++) {
            int col = n * 8 + 2 * t;
            float2 p0 = *(const float2*)(Ob + r0l * 66 + col);
            float2 p1 = *(const float2*)(Ob + r1l * 66 + col);
            float y00 = (O[n][0] + p0.x) * inv0;
            float y01 = (O[n][1] + p0.y) * inv0;
            float y10 = (O[n][2] + p1.x) * inv1;
            float y11 = (O[n][3] + p1.y) * inv1;
            *(float2*)(yo + (size_t)qrow0 * HD + col) = make_float2(y00, y01);
            *(float2*)(yo + (size_t)qrow1 * HD + col) = make_float2(y10, y11);
            float e00 = 0.f, e01 = 0.f, e10 = 0.f, e11 = 0.f;
            if (qrow0 + 1 < TT) {
                float2 xv = *(const float2*)(vx + (size_t)(qrow0 + 1) * TC + col);
                e00 = xv.x - y00; e01 = xv.y - y01;
            }
            if (qrow1 + 1 < TT) {
                float2 xv = *(const float2*)(vx + (size_t)(qrow1 + 1) * TC + col);
                e10 = xv.x - y10; e11 = xv.y - y11;
            }
            eo[vfrag_idx(qrow0, col)]     = f2tf32(e00);
            eo[vfrag_idx(qrow0, col + 1)] = f2tf32(e01);
            eo[vfrag_idx(qrow1, col)]     = f2tf32(e10);
            eo[vfrag_idx(qrow1, col + 1)] = f2tf32(e11);
        }
    }
}

// ---------------------------------------------------------------------------
// ARMA attention: round-13 form. 1xTF32 S, 1xTF32 PV, 3 CTAs/SM,
// single-buffered 64-row tiles. smem 49152 B.
// ---------------------------------------------------------------------------
__global__ __launch_bounds__(256, 3)
void arma_kernel()
{
    extern __shared__ uint32_t smu[];
    uint32_t* Qa = smu;
    uint32_t* Ka = Qa + 4096;
    uint32_t* Vv = Ka + 4096;

    const int tid = threadIdx.x;
    const int lane = tid & 31;
    const int warp = tid >> 5;
    const int wm = warp >> 1;
    const int wn = warp & 1;
    const int g = lane >> 2;
    const int t = lane & 3;

    const int bh = blockIdx.y;
    const int b = bh >> 4, h = bh & 15;
    const int qb = (int)gridDim.x - 1 - (int)blockIdx.x;
    const int q0 = qb * 64;

    const size_t bhoff = (size_t)bh * (TT * 64);
    const uint32_t* ka_g = g_kah + bhoff;
    const uint32_t* e_g  = g_e32 + bhoff;
    const float* yb = g_y + (size_t)bh * TT * HD;

    const uint32_t Ka_s = s2u(Ka), Vv_s = s2u(Vv);

    {
        const uint32_t* qhT = g_qsh + bhoff + (size_t)q0 * 64;
        const uint32_t* qlT = g_qsl + bhoff + (size_t)q0 * 64;
#pragma unroll
        for (int k = 0; k < 4; k++) {
            int o = (tid + k * 256) * 4;
            uint4 hv = *(const uint4*)(qhT + o);
            uint4 lv = *(const uint4*)(qlT + o);
            float q0f = __uint_as_float(hv.x) + __uint_as_float(lv.x);
            float q1f = __uint_as_float(hv.y) + __uint_as_float(lv.y);
            float q2f = __uint_as_float(hv.z) + __uint_as_float(lv.z);
            float q3f = __uint_as_float(hv.w) + __uint_as_float(lv.w);
            *(uint4*)(Qa + o) = make_uint4(
                f2tf32(fminf(q0f, 0.02f * q0f)),
                f2tf32(fminf(q1f, 0.02f * q1f)),
                f2tf32(fminf(q2f, 0.02f * q2f)),
                f2tf32(fminf(q3f, 0.02f * q3f)));
        }
    }

    float O[8][4];
#pragma unroll
    for (int n = 0; n < 8; n++)
#pragma unroll
        for (int c = 0; c < 4; c++) O[n][c] = 0.f;

    const int qrow0 = q0 + wm * 16 + g;
    const int qrow1 = qrow0 + 8;
    const int sw = wn * 32;

    for (int kt = 0; kt <= qb; kt++) {
        const int s0 = kt * 64;
        __syncthreads();

        {
            const uint32_t* kT = ka_g + (size_t)s0 * 64;
            const uint32_t* vT = e_g + (size_t)s0 * 64;
#pragma unroll
            for (int k = 0; k < 4; k++) {
                int o = (tid + k * 256) * 4;
                cp_async16(Ka_s + o * 4, kT + o);
                cp_async16(Vv_s + o * 4, vT + o);
            }
        }
        CP_COMMIT();
        CP_WAIT0();
        __syncthreads();

        float acc[4][4];
#pragma unroll
        for (int nb = 0; nb < 4; nb++)
#pragma unroll
            for (int c = 0; c < 4; c++) acc[nb][c] = 0.f;

#pragma unroll
        for (int c = 0; c < 8; c++) {
            int qoff = wm * 1024 + lane * 32 + ((c + (lane & 7)) & 7) * 4;
            uint4 ahv = *(const uint4*)(Qa + qoff);
            uint32_t ah[4] = {ahv.x, ahv.y, ahv.z, ahv.w};
#pragma unroll
            for (int nb = 0; nb < 4; nb++) {
                int koff = (wn * 4 + nb) * 512 + lane * 16
                         + ((c + (lane >> 1)) & 7) * 2;
                uint2 kk = *(const uint2*)(Ka + koff);
                uint32_t bv[2] = {kk.x, kk.y};
                mma_tf32(acc[nb], ah, bv);
            }
        }

        if (kt == qb) {
#pragma unroll
            for (int nb = 0; nb < 4; nb++) {
                int colb = s0 + sw + nb * 8 + 2 * t;
#pragma unroll
                for (int c = 0; c < 4; c++) {
                    int cc = colb + (c & 1);
                    int rr = (c >= 2) ? qrow1 : qrow0;
                    if (cc >= rr) acc[nb][c] = 0.f;
                }
            }
        }

#pragma unroll
        for (int nb = 0; nb < 4; nb++) {
            int src0 = (lane & ~3) | (t >> 1);
            int src2 = src0 + 2;
            float s00 = __shfl_sync(0xffffffffu, acc[nb][0], src0);
            float s01 = __shfl_sync(0xffffffffu, acc[nb][1], src0);
            float s20 = __shfl_sync(0xffffffffu, acc[nb][0], src2);
            float s21 = __shfl_sync(0xffffffffu, acc[nb][1], src2);
            float s10 = __shfl_sync(0xffffffffu, acc[nb][2], src0);
            float s11 = __shfl_sync(0xffffffffu, acc[nb][3], src0);
            float s30 = __shfl_sync(0xffffffffu, acc[nb][2], src2);
            float s31 = __shfl_sync(0xffffffffu, acc[nb][3], src2);
            bool odd = (t & 1);
            uint32_t ah[4];
            ah[0] = f2tf32(odd ? s01 : s00);
            ah[1] = f2tf32(odd ? s11 : s10);
            ah[2] = f2tf32(odd ? s21 : s20);
            ah[3] = f2tf32(odd ? s31 : s30);

            int vb = (wn * 4 + nb) * 512 + lane * 16;
            uint32_t vfr[16];
#pragma unroll
            for (int G = 0; G < 4; G++) {
                uint4 t4 = *(const uint4*)(Vv + vb + ((G + (lane >> 1)) & 3) * 4);
                vfr[G * 4 + 0] = t4.x; vfr[G * 4 + 1] = t4.y;
                vfr[G * 4 + 2] = t4.z; vfr[G * 4 + 3] = t4.w;
            }
#pragma unroll
            for (int n = 0; n < 8; n++) {
                uint32_t bv[2] = {vfr[n], vfr[8 + n]};
                mma_tf32(O[n], ah, bv);
            }
        }
    }

    __syncthreads();
    const int r0l = wm * 16 + g, r1l = r0l + 8;
    float* Ob = (float*)smu;
    if (wn == 1) {
#pragma unroll
        for (int n = 0; n < 8; n++) {
            int col = n * 8 + 2 * t;
            *(float2*)(Ob + r0l * 66 + col) = make_float2(O[n][0], O[n][1]);
            *(float2*)(Ob + r1l * 66 + col) = make_float2(O[n][2], O[n][3]);
        }
    }
    __syncthreads();
    if (wn == 0) {
        uint32_t* yo = g_ysumt + (size_t)b * TT * TC + h * HD;
#pragma unroll
        for (int n = 0; n < 8; n++) {
            int col = n * 8 + 2 * t;
            float2 p0 = *(const float2*)(Ob + r0l * 66 + col);
            float2 p1 = *(const float2*)(Ob + r1l * 66 + col);
            float2 y0 = *(const float2*)(yb + (size_t)qrow0 * HD + col);
            float2 y1 = *(const float2*)(yb + (size_t)qrow1 * HD + col);
            *(uint2*)(yo + (size_t)qrow0 * TC + col) =
                make_uint2(f2tf32(O[n][0] + p0.x + y0.x),
                           f2tf32(O[n][1] + p0.y + y0.y));
            *(uint2*)(yo + (size_t)qrow1 * TC + col) =
                make_uint2(f2tf32(O[n][2] + p1.x + y1.x),
                           f2tf32(O[n][3] + p1.y + y1.y));
        }
    }
}

// ---------------------------------------------------------------------------
extern "C" void kernel_launch(void* const* d_in, const int* in_sizes, int n_in,
                              void* d_out, int out_size)
{
    (void)in_sizes; (void)n_in; (void)out_size;
    const float* x      = (const float*)d_in[0];
    const float* W_attn = (const float*)d_in[1];
    const float* W_k2   = (const float*)d_in[2];
    const float* W_proj = (const float*)d_in[3];
    float* out = (float*)d_out;

    const int smem_attn = 12288 * (int)sizeof(uint32_t);  // 49152 B
    const int smem_arma = 12288 * (int)sizeof(uint32_t);  // 49152 B
    const int smem_gemm = (3 * 2560 + 3 * 2176) * (int)sizeof(uint32_t);
    cudaFuncSetAttribute(fattn_kernel,
                         cudaFuncAttributeMaxDynamicSharedMemorySize, smem_attn);
    cudaFuncSetAttribute(arma_kernel,
                         cudaFuncAttributeMaxDynamicSharedMemorySize, smem_arma);
    cudaFuncSetAttribute(tgemm_kernel<0>,
                         cudaFuncAttributeMaxDynamicSharedMemorySize, smem_gemm);
    cudaFuncSetAttribute(tgemm_kernel<2>,
                         cudaFuncAttributeMaxDynamicSharedMemorySize, smem_gemm);

    prep_all_kernel<<<9216, 256>>>(x, W_attn, W_k2, W_proj);
    tgemm_kernel<0><<<dim3(3 * TC / 128, MROWS / 128), 256, smem_gemm>>>(
        nullptr, MROWS, 3 * TC, TC);
    fattn_kernel<<<dim3(TT / 64, BHN), 256, smem_attn>>>(x);
    arma_kernel<<<dim3(TT / 64, BHN), 256, smem_arma>>>();
    tgemm_kernel<2><<<dim3(TC / 128, MROWS / 128), 256, smem_gemm>>>(
        out, MROWS, TC, TC);
}

// round 16
// speedup vs baseline: 1.0836x; 1.0085x over previous
#include <cuda_runtime.h>
#include <math.h>
#include <stdint.h>

#define TB 2
#define TT 2048
#define TC 1024
#define NH 16
#define HD 64
#define BHN (TB*NH)
#define MROWS (TB*TT)
#define SCALE 0.125f

#define NELEM ((size_t)BHN*TT*HD)

// Frag-major attention operands (tf32 words)
__device__ __align__(16) uint32_t g_qsh[NELEM];    // q*scale hi, Q-frag layout
__device__ __align__(16) uint32_t g_qah[NELEM];    // qa hi, Q-frag layout
__device__ __align__(16) uint32_t g_kfr[NELEM];    // k hi, paired K-frag layout
__device__ __align__(16) uint32_t g_kah[NELEM];    // ka hi, paired K-frag layout
__device__ __align__(16) uint32_t g_v32[NELEM];    // tf32(x) V-frag layout
__device__ __align__(16) uint32_t g_e32[NELEM];    // tf32(x[s+1]-y[s])
__device__ __align__(16) float    g_y[NELEM];
// tf32 GEMM operands (pre-converted once)
__device__ __align__(16) uint32_t g_xt[(size_t)MROWS*TC];
__device__ __align__(16) uint32_t g_wat[(size_t)TC*2*TC];
__device__ __align__(16) uint32_t g_wk2[(size_t)TC*TC];
__device__ __align__(16) uint32_t g_wpr[(size_t)TC*TC];
__device__ __align__(16) uint32_t g_ysumt[(size_t)TB*TT*TC];

__device__ __forceinline__ uint32_t f2tf32(float f) {
    uint32_t u;
    asm volatile("cvt.rna.tf32.f32 %0, %1;" : "=r"(u) : "f"(f));
    return u;
}
__device__ __forceinline__ void mma_tf32(float c[4], const uint32_t a[4],
                                         const uint32_t b[2]) {
    asm volatile(
        "mma.sync.aligned.m16n8k8.row.col.f32.tf32.tf32.f32 "
        "{%0,%1,%2,%3}, {%4,%5,%6,%7}, {%8,%9}, {%0,%1,%2,%3};"
        : "+f"(c[0]), "+f"(c[1]), "+f"(c[2]), "+f"(c[3])
        : "r"(a[0]), "r"(a[1]), "r"(a[2]), "r"(a[3]), "r"(b[0]), "r"(b[1]));
}
__device__ __forceinline__ uint32_t s2u(const void* p) {
    return (uint32_t)__cvta_generic_to_shared(p);
}
__device__ __forceinline__ void cp_async16(uint32_t dst, const void* src) {
    asm volatile("cp.async.cg.shared.global [%0], [%1], 16;"
                 :: "r"(dst), "l"(src));
}
#define CP_COMMIT() asm volatile("cp.async.commit_group;")
#define CP_WAIT0()  asm volatile("cp.async.wait_group 0;" ::: "memory")
#define CP_WAIT1()  asm volatile("cp.async.wait_group 1;" ::: "memory")

// ---- frag-layout index helpers ----
__device__ __forceinline__ size_t qfrag_idx(int tt, int dd) {
    int lane = ((tt & 7) << 2) | (dd & 3);
    int word = (((dd >> 3) + (lane & 7)) & 7) * 4
             + ((tt >> 3) & 1) + (((dd >> 2) & 1) << 1);
    return ((size_t)(tt >> 4)) * 1024 + lane * 32 + word;
}
// paired K frag: one uint4 = two consecutive k-steps {c.h0, c.h1, c+1.h0, c+1.h1}
__device__ __forceinline__ size_t kfrag_idx(int s, int d) {
    int lane = ((s & 7) << 2) | (d & 3);
    int word = (((d >> 4) + (lane >> 1)) & 3) * 4
             + (((d >> 3) & 1) << 1) + ((d >> 2) & 1);
    return ((size_t)(s >> 3)) * 512 + lane * 16 + word;
}
__device__ __forceinline__ size_t vfrag_idx(int s, int d) {
    int lane = ((d & 7) << 2) | (s & 3);
    int n = d >> 3;
    int grp = ((s >> 2) & 1) * 2 + (n >> 2);
    int word = ((grp + (lane >> 1)) & 3) * 4 + (n & 3);
    return ((size_t)(s >> 3)) * 512 + lane * 16 + word;
}
__device__ __forceinline__ void store_q(int bh, int tt, int dd, float qraw) {
    float qs = qraw * SCALE;
    size_t f = (size_t)bh * (TT * 64) + qfrag_idx(tt, dd);
    g_qsh[f] = f2tf32(qs);
    float qa = fminf(qs, 0.02f * qs);
    g_qah[f] = f2tf32(qa);
}

// ---------------------------------------------------------------------------
// ONE prep kernel: tf32 conversions + V-frag scatter (block-range dispatch)
// ---------------------------------------------------------------------------
__global__ __launch_bounds__(256)
void prep_all_kernel(const float* __restrict__ x,
                     const float* __restrict__ W_attn,
                     const float* __restrict__ W_k2,
                     const float* __restrict__ W_proj)
{
    __shared__ uint32_t vs[4096];
    const int bid = blockIdx.x;
    const int tid = threadIdx.x;

    if (bid < 8192) {
        const float* src;
        uint32_t* dst;
        size_t i;
        if (bid < 4096)      { src = x;      dst = g_xt;  i = (size_t)bid * 256 + tid; }
        else if (bid < 6144) { src = W_attn; dst = g_wat; i = (size_t)(bid - 4096) * 256 + tid; }
        else if (bid < 7168) { src = W_k2;   dst = g_wk2; i = (size_t)(bid - 6144) * 256 + tid; }
        else                 { src = W_proj; dst = g_wpr; i = (size_t)(bid - 7168) * 256 + tid; }
        float4 v = ((const float4*)src)[i];
        ((uint4*)dst)[i] = make_uint4(f2tf32(v.x), f2tf32(v.y),
                                      f2tf32(v.z), f2tf32(v.w));
    } else {
        int p = bid - 8192;
        int s0 = (p & 31) * 64;
        int bh = p >> 5;
        int b = bh >> 4, h = bh & 15;
        int lr = tid >> 4, lc4 = (tid & 15) << 2;
#pragma unroll
        for (int it = 0; it < 4; it++) {
            int r = lr + it * 16;
            float4 v = *(const float4*)(x + ((size_t)b * TT + s0 + r) * TC + h * 64 + lc4);
            vs[vfrag_idx(r, lc4 + 0)] = f2tf32(v.x);
            vs[vfrag_idx(r, lc4 + 1)] = f2tf32(v.y);
            vs[vfrag_idx(r, lc4 + 2)] = f2tf32(v.z);
            vs[vfrag_idx(r, lc4 + 3)] = f2tf32(v.w);
        }
        __syncthreads();
        uint32_t* dst = g_v32 + (size_t)bh * (TT * 64) + (size_t)s0 * 64;
#pragma unroll
        for (int k = 0; k < 4; k++) {
            int o = (tid + k * 256) * 4;
            *(uint4*)(dst + o) = *(const uint4*)(vs + o);
        }
    }
}

// ---------------------------------------------------------------------------
// TF32 GEMM, 3-stage cp.async pipeline. (main loop unchanged)
// ---------------------------------------------------------------------------
template<int MODE>
__global__ __launch_bounds__(256)
void tgemm_kernel(float* __restrict__ Cout, int M, int N, int K)
{
    extern __shared__ uint32_t smg[];
    const int tid = threadIdx.x;
    const int lane = tid & 31;
    const int warp = tid >> 5;
    const int warpM = warp >> 2, warpN = warp & 3;
    const int g = lane >> 2, t = lane & 3;
    const int bm = blockIdx.y * 128, bn = blockIdx.x * 128;

    const uint32_t* Ap = (MODE == 2) ? g_ysumt : g_xt;
    const uint32_t* Bw;
    int Nb, bnn;
    if (MODE == 0) {
        if (bn < 2 * TC) { Bw = g_wat; Nb = 2 * TC; bnn = bn; }
        else             { Bw = g_wk2; Nb = TC;     bnn = bn - 2 * TC; }
    } else {
        Bw = g_wpr; Nb = N; bnn = bn;
    }

    float acc[4][4][4];
#pragma unroll
    for (int i = 0; i < 4; i++)
#pragma unroll
        for (int j = 0; j < 4; j++)
#pragma unroll
            for (int r = 0; r < 4; r++) acc[i][j][r] = 0.f;

    auto issue = [&](int kt, int st) {
#pragma unroll
        for (int l = 0; l < 2; l++) {
            int id = tid + l * 256;
            int ar = id >> 2, ak = (id & 3) << 2;
            cp_async16(s2u(smg + st * 2560 + ar * 20 + ak),
                       Ap + (size_t)(bm + ar) * K + kt + ak);
            int br = id >> 5, bc = (id & 31) << 2;
            cp_async16(s2u(smg + 7680 + st * 2176 + br * 136 + bc),
                       Bw + (size_t)(kt + br) * Nb + bnn + bc);
        }
        CP_COMMIT();
    };

    issue(0, 0);
    issue(16, 1);
    const int nk = K >> 4;

    for (int i = 0; i < nk; i++) {
        const int st = i % 3;
        const uint32_t* Asb = smg + st * 2560;
        const uint32_t* Bsb = smg + 7680 + st * 2176;
        if (i + 1 < nk) { CP_WAIT1(); } else { CP_WAIT0(); }
        __syncthreads();
#pragma unroll
        for (int ks = 0; ks < 2; ks++) {
            const int k0 = ks * 8;
            uint32_t af[4][4], bf[4][2];
#pragma unroll
            for (int i4 = 0; i4 < 4; i4++) {
                int m0 = warpM * 64 + i4 * 16;
                af[i4][0] = Asb[(m0 + g) * 20 + k0 + t];
                af[i4][1] = Asb[(m0 + g + 8) * 20 + k0 + t];
                af[i4][2] = Asb[(m0 + g) * 20 + k0 + t + 4];
                af[i4][3] = Asb[(m0 + g + 8) * 20 + k0 + t + 4];
            }
#pragma unroll
            for (int j = 0; j < 4; j++) {
                int n0 = warpN * 32 + j * 8;
                bf[j][0] = Bsb[(k0 + t) * 136 + n0 + g];
                bf[j][1] = Bsb[(k0 + t + 4) * 136 + n0 + g];
            }
#pragma unroll
            for (int i4 = 0; i4 < 4; i4++)
#pragma unroll
                for (int j = 0; j < 4; j++)
                    mma_tf32(acc[i4][j], af[i4], bf[j]);
        }
        if (i + 2 < nk) issue((i + 2) << 4, (i + 2) % 3);
    }

    // epilogue
#pragma unroll
    for (int i = 0; i < 4; i++) {
#pragma unroll
        for (int j = 0; j < 4; j++) {
            int col = bn + warpN * 32 + j * 8 + t * 2;
#pragma unroll
            for (int half = 0; half < 2; half++) {
                int m = bm + warpM * 64 + i * 16 + g + half * 8;
                float2 v = half == 0 ? make_float2(acc[i][j][0], acc[i][j][1])
                                     : make_float2(acc[i][j][2], acc[i][j][3]);
                if (MODE == 2) {
                    *(float2*)(Cout + (size_t)m * N + col) = v;
                } else {
                    int b = m >> 11;
                    int tt = m & (TT - 1);
                    if (col < TC) {
                        int bh = b * NH + (col >> 6);
                        int dd = col & 63;
                        store_q(bh, tt, dd, v.x);
                        store_q(bh, tt, dd + 1, v.y);
                    } else if (col < 2 * TC) {
                        int nn = col - TC;
                        int bh = b * NH + (nn >> 6);
                        int dd = nn & 63;
                        size_t base = (size_t)bh * (TT * 64);
                        g_kfr[base + kfrag_idx(tt, dd)]     = f2tf32(v.x);
                        g_kfr[base + kfrag_idx(tt, dd + 1)] = f2tf32(v.y);
                    } else {
                        int nn = col - 2 * TC;
                        int bh = b * NH + (nn >> 6);
                        int dd = nn & 63;
                        float ka0 = 1.f / (1.f + __expf(-0.0025f * v.x));
                        float ka1 = 1.f / (1.f + __expf(-0.0025f * v.y));
                        size_t base = (size_t)bh * (TT * 64);
                        g_kah[base + kfrag_idx(tt, dd)]     = f2tf32(ka0);
                        g_kah[base + kfrag_idx(tt, dd + 1)] = f2tf32(ka1);
                    }
                }
            }
        }
    }
}

// ---------------------------------------------------------------------------
// Softmax flash attention. S = 1xTF32, paired-K uint4 loads; PV = 1xTF32.
// smem: Qh(4096) + Kf(4096) + Vv(4096) = 49152 B -> 3 CTAs/SM.
// ---------------------------------------------------------------------------
__global__ __launch_bounds__(256, 3)
void fattn_kernel(const float* __restrict__ x)
{
    extern __shared__ uint32_t smu[];
    uint32_t* Qh = smu;
    uint32_t* Kf = Qh + 4096;
    uint32_t* Vv = Kf + 4096;

    const int tid = threadIdx.x;
    const int lane = tid & 31;
    const int warp = tid >> 5;
    const int wm = warp >> 1;
    const int wn = warp & 1;
    const int g = lane >> 2;
    const int t = lane & 3;

    const int bh = blockIdx.y;
    const int b = bh >> 4, h = bh & 15;
    const int qb = (int)gridDim.x - 1 - (int)blockIdx.x;
    const int q0 = qb * 64;

    const size_t bhoff = (size_t)bh * (TT * 64);
    const uint32_t* kf_g = g_kfr + bhoff;
    const uint32_t* v_g  = g_v32 + bhoff;
    const float* vx = x + (size_t)b * TT * TC + h * HD;

    const uint32_t Qh_s = s2u(Qh);
    const uint32_t Kf_s = s2u(Kf), Vv_s = s2u(Vv);

    {
        const uint32_t* qhT = g_qsh + bhoff + (size_t)q0 * 64;
#pragma unroll
        for (int k = 0; k < 4; k++) {
            int o = (tid + k * 256) * 4;
            cp_async16(Qh_s + o * 4, qhT + o);
        }
    }

    float O[8][4];
#pragma unroll
    for (int n = 0; n < 8; n++)
#pragma unroll
        for (int c = 0; c < 4; c++) O[n][c] = 0.f;
    float m_run[2] = {-1e30f, -1e30f};
    float l_run[2] = {0.f, 0.f};

    const int qrow0 = q0 + wm * 16 + g;
    const int qrow1 = qrow0 + 8;
    const int sw = wn * 32;

    for (int kt = 0; kt <= qb; kt++) {
        const int s0 = kt * 64;
        __syncthreads();

        {
            const uint32_t* kT = kf_g + (size_t)s0 * 64;
            const uint32_t* vT = v_g + (size_t)s0 * 64;
#pragma unroll
            for (int k = 0; k < 4; k++) {
                int o = (tid + k * 256) * 4;
                cp_async16(Kf_s + o * 4, kT + o);
                cp_async16(Vv_s + o * 4, vT + o);
            }
        }
        CP_COMMIT();
        CP_WAIT0();
        __syncthreads();

        // ---- S = Q @ K^T : 1xTF32, paired K (uint4 = 2 k-steps)
        float acc[4][4];
#pragma unroll
        for (int nb = 0; nb < 4; nb++)
#pragma unroll
            for (int c = 0; c < 4; c++) acc[nb][c] = 0.f;

#pragma unroll
        for (int c2 = 0; c2 < 4; c2++) {
            const int c0 = 2 * c2, c1 = 2 * c2 + 1;
            int qoff0 = wm * 1024 + lane * 32 + ((c0 + (lane & 7)) & 7) * 4;
            int qoff1 = wm * 1024 + lane * 32 + ((c1 + (lane & 7)) & 7) * 4;
            uint4 a0v = *(const uint4*)(Qh + qoff0);
            uint4 a1v = *(const uint4*)(Qh + qoff1);
            uint32_t ah0[4] = {a0v.x, a0v.y, a0v.z, a0v.w};
            uint32_t ah1[4] = {a1v.x, a1v.y, a1v.z, a1v.w};
#pragma unroll
            for (int nb = 0; nb < 4; nb++) {
                int koff = (wn * 4 + nb) * 512 + lane * 16
                         + ((c2 + (lane >> 1)) & 3) * 4;
                uint4 kk = *(const uint4*)(Kf + koff);
                uint32_t b0[2] = {kk.x, kk.y};
                uint32_t b1[2] = {kk.z, kk.w};
                mma_tf32(acc[nb], ah0, b0);
                mma_tf32(acc[nb], ah1, b1);
            }
        }

        const bool diag = (kt == qb);
        if (diag) {
#pragma unroll
            for (int nb = 0; nb < 4; nb++) {
                int colb = s0 + sw + nb * 8 + 2 * t;
#pragma unroll
                for (int c = 0; c < 4; c++) {
                    int cc = colb + (c & 1);
                    int rr = (c >= 2) ? qrow1 : qrow0;
                    if (cc > rr) acc[nb][c] = -1e30f;
                }
            }
        }

        float mt0 = -1e30f, mt1 = -1e30f;
#pragma unroll
        for (int nb = 0; nb < 4; nb++) {
            mt0 = fmaxf(mt0, fmaxf(acc[nb][0], acc[nb][1]));
            mt1 = fmaxf(mt1, fmaxf(acc[nb][2], acc[nb][3]));
        }
#pragma unroll
        for (int off = 1; off <= 2; off <<= 1) {
            mt0 = fmaxf(mt0, __shfl_xor_sync(0xffffffffu, mt0, off));
            mt1 = fmaxf(mt1, __shfl_xor_sync(0xffffffffu, mt1, off));
        }
        float mn0 = fmaxf(m_run[0], mt0);
        float mn1 = fmaxf(m_run[1], mt1);
        float corr0 = __expf(m_run[0] - mn0);
        float corr1 = __expf(m_run[1] - mn1);
        m_run[0] = mn0; m_run[1] = mn1;

        float ls0 = 0.f, ls1 = 0.f;
#pragma unroll
        for (int nb = 0; nb < 4; nb++) {
            float p0 = __expf(acc[nb][0] - mn0);
            float p1 = __expf(acc[nb][1] - mn0);
            float p2 = __expf(acc[nb][2] - mn1);
            float p3 = __expf(acc[nb][3] - mn1);
            if (diag) {
                int colb = s0 + sw + nb * 8 + 2 * t;
                if (colb     > qrow0) p0 = 0.f;
                if (colb + 1 > qrow0) p1 = 0.f;
                if (colb     > qrow1) p2 = 0.f;
                if (colb + 1 > qrow1) p3 = 0.f;
            }
            acc[nb][0] = p0; acc[nb][1] = p1;
            acc[nb][2] = p2; acc[nb][3] = p3;
            ls0 += p0 + p1;
            ls1 += p2 + p3;
        }
#pragma unroll
        for (int off = 1; off <= 2; off <<= 1) {
            ls0 += __shfl_xor_sync(0xffffffffu, ls0, off);
            ls1 += __shfl_xor_sync(0xffffffffu, ls1, off);
        }
        l_run[0] = l_run[0] * corr0 + ls0;
        l_run[1] = l_run[1] * corr1 + ls1;
#pragma unroll
        for (int n = 0; n < 8; n++) {
            O[n][0] *= corr0; O[n][1] *= corr0;
            O[n][2] *= corr1; O[n][3] *= corr1;
        }

        // ---- O += P @ V : P hi-only (1xTF32)
#pragma unroll
        for (int nb = 0; nb < 4; nb++) {
            int src0 = (lane & ~3) | (t >> 1);
            int src2 = src0 + 2;
            float s00 = __shfl_sync(0xffffffffu, acc[nb][0], src0);
            float s01 = __shfl_sync(0xffffffffu, acc[nb][1], src0);
            float s20 = __shfl_sync(0xffffffffu, acc[nb][0], src2);
            float s21 = __shfl_sync(0xffffffffu, acc[nb][1], src2);
            float s10 = __shfl_sync(0xffffffffu, acc[nb][2], src0);
            float s11 = __shfl_sync(0xffffffffu, acc[nb][3], src0);
            float s30 = __shfl_sync(0xffffffffu, acc[nb][2], src2);
            float s31 = __shfl_sync(0xffffffffu, acc[nb][3], src2);
            bool odd = (t & 1);
            uint32_t ah[4];
            ah[0] = f2tf32(odd ? s01 : s00);
            ah[1] = f2tf32(odd ? s11 : s10);
            ah[2] = f2tf32(odd ? s21 : s20);
            ah[3] = f2tf32(odd ? s31 : s30);

            int vb = (wn * 4 + nb) * 512 + lane * 16;
            uint32_t vfr[16];
#pragma unroll
            for (int G = 0; G < 4; G++) {
                uint4 t4 = *(const uint4*)(Vv + vb + ((G + (lane >> 1)) & 3) * 4);
                vfr[G * 4 + 0] = t4.x; vfr[G * 4 + 1] = t4.y;
                vfr[G * 4 + 2] = t4.z; vfr[G * 4 + 3] = t4.w;
            }
#pragma unroll
            for (int n = 0; n < 8; n++) {
                uint32_t bv[2] = {vfr[n], vfr[8 + n]};
                mma_tf32(O[n], ah, bv);
            }
        }
    }

    __syncthreads();
    const int r0l = wm * 16 + g, r1l = r0l + 8;
    float* Ob = (float*)smu;
    float* ml = (float*)Vv;
    if (t == 0) {
        ml[r0l * 4 + wn * 2 + 0] = m_run[0];
        ml[r0l * 4 + wn * 2 + 1] = l_run[0];
        ml[r1l * 4 + wn * 2 + 0] = m_run[1];
        ml[r1l * 4 + wn * 2 + 1] = l_run[1];
    }
    __syncthreads();
    float ma0 = ml[r0l * 4 + 0], la0 = ml[r0l * 4 + 1];
    float mb0 = ml[r0l * 4 + 2], lb0 = ml[r0l * 4 + 3];
    float ma1 = ml[r1l * 4 + 0], la1 = ml[r1l * 4 + 1];
    float mb1 = ml[r1l * 4 + 2], lb1 = ml[r1l * 4 + 3];
    float mm0 = fmaxf(ma0, mb0), mm1 = fmaxf(ma1, mb1);
    float lt0 = la0 * __expf(ma0 - mm0) + lb0 * __expf(mb0 - mm0);
    float lt1 = la1 * __expf(ma1 - mm1) + lb1 * __expf(mb1 - mm1);
    float f0 = __expf(m_run[0] - mm0);
    float f1 = __expf(m_run[1] - mm1);
#pragma unroll
    for (int n = 0; n < 8; n++) {
        O[n][0] *= f0; O[n][1] *= f0;
        O[n][2] *= f1; O[n][3] *= f1;
    }
    if (wn == 1) {
#pragma unroll
        for (int n = 0; n < 8; n++) {
            int col = n * 8 + 2 * t;
            *(float2*)(Ob + r0l * 66 + col) = make_float2(O[n][0], O[n][1]);
            *(float2*)(Ob + r1l * 66 + col) = make_float2(O[n][2], O[n][3]);
        }
    }
    __syncthreads();
    if (wn == 0) {
        float inv0 = 1.f / lt0, inv1 = 1.f / lt1;
        float* yo = g_y + (size_t)bh * TT * HD;
        uint32_t* eo = g_e32 + bhoff;
#pragma unroll
        for (int n = 0; n < 8; n++) {
            int col = n * 8 + 2 * t;
            float2 p0 = *(const float2*)(Ob + r0l * 66 + col);
            float2 p1 = *(const float2*)(Ob + r1l * 66 + col);
            float y00 = (O[n][0] + p0.x) * inv0;
            float y01 = (O[n][1] + p0.y) * inv0;
            float y10 = (O[n][2] + p1.x) * inv1;
            float y11 = (O[n][3] + p1.y) * inv1;
            *(float2*)(yo + (size_t)qrow0 * HD + col) = make_float2(y00, y01);
            *(float2*)(yo + (size_t)qrow1 * HD + col) = make_float2(y10, y11);
            float e00 = 0.f, e01 = 0.f, e10 = 0.f, e11 = 0.f;
            if (qrow0 + 1 < TT) {
                float2 xv = *(const float2*)(vx + (size_t)(qrow0 + 1) * TC + col);
                e00 = xv.x - y00; e01 = xv.y - y01;
            }
            if (qrow1 + 1 < TT) {
                float2 xv = *(const float2*)(vx + (size_t)(qrow1 + 1) * TC + col);
                e10 = xv.x - y10; e11 = xv.y - y11;
            }
            eo[vfrag_idx(qrow0, col)]     = f2tf32(e00);
            eo[vfrag_idx(qrow0, col + 1)] = f2tf32(e01);
            eo[vfrag_idx(qrow1, col)]     = f2tf32(e10);
            eo[vfrag_idx(qrow1, col + 1)] = f2tf32(e11);
        }
    }
}

// ---------------------------------------------------------------------------
// ARMA attention: 1xTF32 S (paired-K uint4) + 1xTF32 PV; Q staging is pure
// cp.async from g_qah. 3 CTAs/SM, single-buffered 64-row tiles. 49152 B.
// ---------------------------------------------------------------------------
__global__ __launch_bounds__(256, 3)
void arma_kernel()
{
    extern __shared__ uint32_t smu[];
    uint32_t* Qa = smu;
    uint32_t* Ka = Qa + 4096;
    uint32_t* Vv = Ka + 4096;

    const int tid = threadIdx.x;
    const int lane = tid & 31;
    const int warp = tid >> 5;
    const int wm = warp >> 1;
    const int wn = warp & 1;
    const int g = lane >> 2;
    const int t = lane & 3;

    const int bh = blockIdx.y;
    const int b = bh >> 4, h = bh & 15;
    const int qb = (int)gridDim.x - 1 - (int)blockIdx.x;
    const int q0 = qb * 64;

    const size_t bhoff = (size_t)bh * (TT * 64);
    const uint32_t* ka_g = g_kah + bhoff;
    const uint32_t* e_g  = g_e32 + bhoff;
    const float* yb = g_y + (size_t)bh * TT * HD;

    const uint32_t Qa_s = s2u(Qa), Ka_s = s2u(Ka), Vv_s = s2u(Vv);

    {
        const uint32_t* qaT = g_qah + bhoff + (size_t)q0 * 64;
#pragma unroll
        for (int k = 0; k < 4; k++) {
            int o = (tid + k * 256) * 4;
            cp_async16(Qa_s + o * 4, qaT + o);
        }
    }

    float O[8][4];
#pragma unroll
    for (int n = 0; n < 8; n++)
#pragma unroll
        for (int c = 0; c < 4; c++) O[n][c] = 0.f;

    const int qrow0 = q0 + wm * 16 + g;
    const int qrow1 = qrow0 + 8;
    const int sw = wn * 32;

    for (int kt = 0; kt <= qb; kt++) {
        const int s0 = kt * 64;
        __syncthreads();

        {
            const uint32_t* kT = ka_g + (size_t)s0 * 64;
            const uint32_t* vT = e_g + (size_t)s0 * 64;
#pragma unroll
            for (int k = 0; k < 4; k++) {
                int o = (tid + k * 256) * 4;
                cp_async16(Ka_s + o * 4, kT + o);
                cp_async16(Vv_s + o * 4, vT + o);
            }
        }
        CP_COMMIT();
        CP_WAIT0();
        __syncthreads();

        // ---- S = Qa @ Ka^T : 1xTF32, paired K
        float acc[4][4];
#pragma unroll
        for (int nb = 0; nb < 4; nb++)
#pragma unroll
            for (int c = 0; c < 4; c++) acc[nb][c] = 0.f;

#pragma unroll
        for (int c2 = 0; c2 < 4; c2++) {
            const int c0 = 2 * c2, c1 = 2 * c2 + 1;
            int qoff0 = wm * 1024 + lane * 32 + ((c0 + (lane & 7)) & 7) * 4;
            int qoff1 = wm * 1024 + lane * 32 + ((c1 + (lane & 7)) & 7) * 4;
            uint4 a0v = *(const uint4*)(Qa + qoff0);
            uint4 a1v = *(const uint4*)(Qa + qoff1);
            uint32_t ah0[4] = {a0v.x, a0v.y, a0v.z, a0v.w};
            uint32_t ah1[4] = {a1v.x, a1v.y, a1v.z, a1v.w};
#pragma unroll
            for (int nb = 0; nb < 4; nb++) {
                int koff = (wn * 4 + nb) * 512 + lane * 16
                         + ((c2 + (lane >> 1)) & 3) * 4;
                uint4 kk = *(const uint4*)(Ka + koff);
                uint32_t b0[2] = {kk.x, kk.y};
                uint32_t b1[2] = {kk.z, kk.w};
                mma_tf32(acc[nb], ah0, b0);
                mma_tf32(acc[nb], ah1, b1);
            }
        }

        if (kt == qb) {
#pragma unroll
            for (int nb = 0; nb < 4; nb++) {
                int colb = s0 + sw + nb * 8 + 2 * t;
#pragma unroll
                for (int c = 0; c < 4; c++) {
                    int cc = colb + (c & 1);
                    int rr = (c >= 2) ? qrow1 : qrow0;
                    if (cc >= rr) acc[nb][c] = 0.f;
                }
            }
        }

#pragma unroll
        for (int nb = 0; nb < 4; nb++) {
            int src0 = (lane & ~3) | (t >> 1);
            int src2 = src0 + 2;
            float s00 = __shfl_sync(0xffffffffu, acc[nb][0], src0);
            float s01 = __shfl_sync(0xffffffffu, acc[nb][1], src0);
            float s20 = __shfl_sync(0xffffffffu, acc[nb][0], src2);
            float s21 = __shfl_sync(0xffffffffu, acc[nb][1], src2);
            float s10 = __shfl_sync(0xffffffffu, acc[nb][2], src0);
            float s11 = __shfl_sync(0xffffffffu, acc[nb][3], src0);
            float s30 = __shfl_sync(0xffffffffu, acc[nb][2], src2);
            float s31 = __shfl_sync(0xffffffffu, acc[nb][3], src2);
            bool odd = (t & 1);
            uint32_t ah[4];
            ah[0] = f2tf32(odd ? s01 : s00);
            ah[1] = f2tf32(odd ? s11 : s10);
            ah[2] = f2tf32(odd ? s21 : s20);
            ah[3] = f2tf32(odd ? s31 : s30);

            int vb = (wn * 4 + nb) * 512 + lane * 16;
            uint32_t vfr[16];
#pragma unroll
            for (int G = 0; G < 4; G++) {
                uint4 t4 = *(const uint4*)(Vv + vb + ((G + (lane >> 1)) & 3) * 4);
                vfr[G * 4 + 0] = t4.x; vfr[G * 4 + 1] = t4.y;
                vfr[G * 4 + 2] = t4.z; vfr[G * 4 + 3] = t4.w;
            }
#pragma unroll
            for (int n = 0; n < 8; n++) {
                uint32_t bv[2] = {vfr[n], vfr[8 + n]};
                mma_tf32(O[n], ah, bv);
            }
        }
    }

    __syncthreads();
    const int r0l = wm * 16 + g, r1l = r0l + 8;
    float* Ob = (float*)smu;
    if (wn == 1) {
#pragma unroll
        for (int n = 0; n < 8; n++) {
            int col = n * 8 + 2 * t;
            *(float2*)(Ob + r0l * 66 + col) = make_float2(O[n][0], O[n][1]);
            *(float2*)(Ob + r1l * 66 + col) = make_float2(O[n][2], O[n][3]);
        }
    }
    __syncthreads();
    if (wn == 0) {
        uint32_t* yo = g_ysumt + (size_t)b * TT * TC + h * HD;
#pragma unroll
        for (int n = 0; n < 8; n++) {
            int col = n * 8 + 2 * t;
            float2 p0 = *(const float2*)(Ob + r0l * 66 + col);
            float2 p1 = *(const float2*)(Ob + r1l * 66 + col);
            float2 y0 = *(const float2*)(yb + (size_t)qrow0 * HD + col);
            float2 y1 = *(const float2*)(yb + (size_t)qrow1 * HD + col);
            *(uint2*)(yo + (size_t)qrow0 * TC + col) =
                make_uint2(f2tf32(O[n][0] + p0.x + y0.x),
                           f2tf32(O[n][1] + p0.y + y0.y));
            *(uint2*)(yo + (size_t)qrow1 * TC + col) =
                make_uint2(f2tf32(O[n][2] + p1.x + y1.x),
                           f2tf32(O[n][3] + p1.y + y1.y));
        }
    }
}

// ---------------------------------------------------------------------------
extern "C" void kernel_launch(void* const* d_in, const int* in_sizes, int n_in,
                              void* d_out, int out_size)
{
    (void)in_sizes; (void)n_in; (void)out_size;
    const float* x      = (const float*)d_in[0];
    const float* W_attn = (const float*)d_in[1];
    const float* W_k2   = (const float*)d_in[2];
    const float* W_proj = (const float*)d_in[3];
    float* out = (float*)d_out;

    const int smem_attn = 12288 * (int)sizeof(uint32_t);  // 49152 B
    const int smem_gemm = (3 * 2560 + 3 * 2176) * (int)sizeof(uint32_t);
    cudaFuncSetAttribute(fattn_kernel,
                         cudaFuncAttributeMaxDynamicSharedMemorySize, smem_attn);
    cudaFuncSetAttribute(arma_kernel,
                         cudaFuncAttributeMaxDynamicSharedMemorySize, smem_attn);
    cudaFuncSetAttribute(tgemm_kernel<0>,
                         cudaFuncAttributeMaxDynamicSharedMemorySize, smem_gemm);
    cudaFuncSetAttribute(tgemm_kernel<2>,
                         cudaFuncAttributeMaxDynamicSharedMemorySize, smem_gemm);

    prep_all_kernel<<<9216, 256>>>(x, W_attn, W_k2, W_proj);
    tgemm_kernel<0><<<dim3(3 * TC / 128, MROWS / 128), 256, smem_gemm>>>(
        nullptr, MROWS, 3 * TC, TC);
    fattn_kernel<<<dim3(TT / 64, BHN), 256, smem_attn>>>(x);
    arma_kernel<<<dim3(TT / 64, BHN), 256, smem_attn>>>();
    tgemm_kernel<2><<<dim3(TC / 128, MROWS / 128), 256, smem_gemm>>>(
        out, MROWS, TC, TC);
}